// round 6
// baseline (speedup 1.0000x reference)
#include <cuda_runtime.h>

#define BATCH 4096
#define PC 2380
#define RW 16            // padded row width (15 cols + ghost)
#define STR2 244         // channel stride in floats (mult of 4)
#define SSTR 52          // gather staging stride (pos-major), 4-aligned, 2-way banks

// ---- smem layout (float offsets) ----
#define OFF_WDW   0      // 432  conv_w 48x9
#define OFF_CB    432    // 48
#define OFF_WPD   480    // 144  pdw 16x9
#define OFF_BPD   624    // 16
#define OFF_WPF   640    // 16
#define OFF_BPP   656    // 16
#define OFF_BVP   672    // 32
#define OFF_VSUM  704    // 32
#define OFF_CODES 736    // 450 ints -> 1186
#define OFF_WPPT  1188   // 256   ppw transposed [ci][co]
#define OFF_WVPT  1444   // 1024  vpw transposed [ci][co]
#define OFF_RAW   2468   // 48*244 = 11712  (aliased: pp on rows 0..15)
#define OFF_CONV  14180  // 48*244 = 11712  (stag aliases here; rows 0..15 later pd)
#define SMEM_FLOATS 25900
#define SMEM_BYTES  (SMEM_FLOATS * 4)

typedef unsigned long long ull;

__device__ __forceinline__ void ffma2(ull& d, ull a, ull b) {
    asm("fma.rn.f32x2 %0, %1, %2, %0;" : "+l"(d) : "l"(a), "l"(b));
}
__device__ __forceinline__ ull pk2(float x, float y) {
    ull r; asm("mov.b64 %0, {%1, %2};" : "=l"(r) : "f"(x), "f"(y)); return r;
}
__device__ __forceinline__ float2 unpk(ull v) {
    float2 f; asm("mov.b64 {%0, %1}, %2;" : "=f"(f.x), "=f"(f.y) : "l"(v)); return f;
}

// depthwise 3x3, one channel, 4-col strip, output rows [H0,H1), sliding window
template<int H0, int H1>
__device__ __forceinline__ void dwconv4(const float* __restrict__ src,
                                        float* __restrict__ dst,
                                        const float* __restrict__ wk,
                                        float bias, int wg)
{
    const int w0 = wg * 4;
    const bool hasL = (wg > 0), hasR = (wg < 3);
    const float k0=wk[0],k1=wk[1],k2=wk[2],k3=wk[3],k4=wk[4],k5=wk[5],k6=wk[6],k7=wk[7],k8=wk[8];
    float al,a0,a1,a2,a3,ar, bl,b0,b1,b2,b3,br;
    if (H0 > 0) {
        const float* r = src + (H0 - 1) * RW;
        float4 m = *(const float4*)(r + w0);
        al = hasL ? r[w0 - 1] : 0.f;  ar = hasR ? r[w0 + 4] : 0.f;
        a0 = m.x; a1 = m.y; a2 = m.z; a3 = m.w;
    } else { al=a0=a1=a2=a3=ar=0.f; }
    {
        const float* r = src + H0 * RW;
        float4 m = *(const float4*)(r + w0);
        bl = hasL ? r[w0 - 1] : 0.f;  br = hasR ? r[w0 + 4] : 0.f;
        b0 = m.x; b1 = m.y; b2 = m.z; b3 = m.w;
    }
    #pragma unroll
    for (int h = H0; h < H1; h++) {
        float cl, c0, c1, c2, c3, cr;
        if (h + 1 < 15) {
            const float* r = src + (h + 1) * RW;
            float4 m = *(const float4*)(r + w0);
            cl = hasL ? r[w0 - 1] : 0.f;  cr = hasR ? r[w0 + 4] : 0.f;
            c0 = m.x; c1 = m.y; c2 = m.z; c3 = m.w;
        } else { cl = c0 = c1 = c2 = c3 = cr = 0.f; }
        float o0 = bias + al*k0+a0*k1+a1*k2 + bl*k3+b0*k4+b1*k5 + cl*k6+c0*k7+c1*k8;
        float o1 = bias + a0*k0+a1*k1+a2*k2 + b0*k3+b1*k4+b2*k5 + c0*k6+c1*k7+c2*k8;
        float o2 = bias + a1*k0+a2*k1+a3*k2 + b1*k3+b2*k4+b3*k5 + c1*k6+c2*k7+c3*k8;
        float o3 = bias + a2*k0+a3*k1+ar*k2 + b2*k3+b3*k4+br*k5 + c2*k6+c3*k7+cr*k8;
        *(float4*)(dst + h * RW + w0) =
            make_float4(fmaxf(o0,0.f), fmaxf(o1,0.f), fmaxf(o2,0.f), fmaxf(o3,0.f));
        al=bl; a0=b0; a1=b1; a2=b2; a3=b3; ar=br;
        bl=cl; b0=c0; b1=c1; b2=c2; b3=c3; br=cr;
    }
}

extern "C" __global__ void __launch_bounds__(256, 2)
patnet_kernel(const float* __restrict__ emb,
              const float* __restrict__ conv_w, const float* __restrict__ conv_b,
              const float* __restrict__ ppw_w,  const float* __restrict__ ppw_b,
              const float* __restrict__ pdw_w,  const float* __restrict__ pdw_b,
              const float* __restrict__ pf_w,
              const float* __restrict__ vpw_w,  const float* __restrict__ vpw_b,
              const float* __restrict__ vl1_w,  const float* __restrict__ vl1_b,
              const float* __restrict__ vl2_w,  const float* __restrict__ vl2_b,
              const float* __restrict__ vf_w,   const float* __restrict__ vf_b,
              const int* __restrict__ sparse,   const int* __restrict__ board,
              float* __restrict__ out)
{
    extern __shared__ float sm[];
    float* wdw  = sm + OFF_WDW;
    float* cb   = sm + OFF_CB;
    float* wpd  = sm + OFF_WPD;
    float* bpd  = sm + OFF_BPD;
    float* wpf  = sm + OFF_WPF;
    float* bpp  = sm + OFF_BPP;
    float* bvp  = sm + OFF_BVP;
    float* vsum = sm + OFF_VSUM;
    int*   codes= (int*)(sm + OFF_CODES);
    float* wppT = sm + OFF_WPPT;
    float* wvpT = sm + OFF_WVPT;
    float* raw  = sm + OFF_RAW;
    float* conv = sm + OFF_CONV;
    float* stag = sm + OFF_CONV;  // pos-major staging, dead before P2 writes conv
    float* pp   = raw;            // rows 0..15, after raw dead
    float* pd   = conv;           // rows 0..15, after pol-pw reads done

    const int tid  = threadIdx.x;
    const int b    = blockIdx.x;
    const int lane = tid & 31;

    // ---------- P0: weights -> smem, codes ----------
    for (int i = tid; i < 432; i += 256) wdw[i] = conv_w[i];
    for (int i = tid; i < 48;  i += 256) cb[i]  = conv_b[i];
    for (int i = tid; i < 144; i += 256) wpd[i] = pdw_w[i];
    if (tid < 16) { bpd[tid] = pdw_b[tid]; wpf[tid] = pf_w[tid]; bpp[tid] = ppw_b[tid]; }
    if (tid >= 32 && tid < 64) { bvp[tid-32] = vpw_b[tid-32]; vsum[tid-32] = 0.0f; }
    for (int i = tid; i < 256; i += 256) {
        int co = i >> 4, ci = i & 15;
        wppT[ci * 16 + co] = ppw_w[i];
    }
    for (int i = tid; i < 1024; i += 256) {
        int co = i >> 5, ci = i & 31;
        wvpT[ci * 32 + co] = vpw_w[i];
    }
    for (int i = tid; i < 450; i += 256) {
        int j = i / 225, p = i - j * 225;
        int sp = sparse[b * 2700 + (10 + j) * 225 + p];
        int bd = board[b * 450 + j * 225 + p];
        int c = (bd > 0) ? PC : sp;
        codes[i] = c + j * (PC + 1);
    }
    __syncthreads();

    // ---------- P1a: coalesced gather, warp per position -> stag[p*52+c] ----------
    {
        const int warpid = tid >> 5;
        const int isHi = (lane >= 12 && lane < 24);
        const int q = isHi ? (lane - 12) : lane;     // quarter index 0..11
        for (int p = warpid; p < 225; p += 8) {
            int code = codes[p + (isHi ? 225 : 0)];
            float4 v = make_float4(0.f, 0.f, 0.f, 0.f);
            if (lane < 24) v = *(const float4*)(emb + code * 48 + q * 4);
            float4 u;
            u.x = __shfl_down_sync(0xffffffffu, v.x, 12);
            u.y = __shfl_down_sync(0xffffffffu, v.y, 12);
            u.z = __shfl_down_sync(0xffffffffu, v.z, 12);
            u.w = __shfl_down_sync(0xffffffffu, v.w, 12);
            if (lane < 12)
                *(float4*)&stag[p * SSTR + lane * 4] =
                    make_float4(v.x + u.x, v.y + u.y, v.z + u.z, v.w + u.w);
        }
    }
    __syncthreads();

    // ---------- P1b: transpose pos-major stag -> ch-major raw (720 tasks) ----------
    if (tid < 240) {
        const int cblk0 = tid / 60;
        const int g = tid - cblk0 * 60;
        const int h = g >> 2, wg = g & 3, w0 = wg * 4;
        #pragma unroll
        for (int task = 0; task < 3; task++) {
            const int cb4 = (cblk0 + task * 4) * 4;
            float4 v[4];
            #pragma unroll
            for (int j = 0; j < 4; j++) {
                int w = w0 + j;
                v[j] = (w < 15) ? *(const float4*)&stag[(h * 15 + w) * SSTR + cb4]
                                : make_float4(0.f, 0.f, 0.f, 0.f);
            }
            float* base = raw + h * RW + w0;
            *(float4*)(base + (cb4+0)*STR2) = make_float4(v[0].x, v[1].x, v[2].x, v[3].x);
            *(float4*)(base + (cb4+1)*STR2) = make_float4(v[0].y, v[1].y, v[2].y, v[3].y);
            *(float4*)(base + (cb4+2)*STR2) = make_float4(v[0].z, v[1].z, v[2].z, v[3].z);
            *(float4*)(base + (cb4+3)*STR2) = make_float4(v[0].w, v[1].w, v[2].w, v[3].w);
        }
    }
    __syncthreads();

    // ---------- P2: main depthwise 3x3, 48 ch, 192 threads ----------
    if (tid < 192) {
        const int c = tid >> 2, wg = tid & 3;
        dwconv4<0, 15>(raw + c * STR2, conv + c * STR2, wdw + c * 9, cb[c], wg);
    }
    __syncthreads();

    // ---------- P3a: value 1x1 32->32, f32x2, S=8 C=4, all 256 threads ----------
    {
        const int cg = tid & 7, pgi = tid >> 3;
        const bool live = (pgi < 30);
        const int p0 = live ? pgi * 8 : 0;
        const int co0 = cg * 4;
        ull acc[4][4];
        {
            float4 bv = *(const float4*)&bvp[co0];
            ull b0 = pk2(bv.x, bv.x), b1 = pk2(bv.y, bv.y);
            ull b2 = pk2(bv.z, bv.z), b3 = pk2(bv.w, bv.w);
            #pragma unroll
            for (int j = 0; j < 4; j++) {
                acc[j][0] = b0; acc[j][1] = b1; acc[j][2] = b2; acc[j][3] = b3;
            }
        }
        #pragma unroll 8
        for (int ci = 0; ci < 32; ci++) {
            const ulonglong2* ip = (const ulonglong2*)&conv[(16 + ci) * STR2 + p0];
            ulonglong2 iA = ip[0], iB = ip[1];
            float4 w4 = *(const float4*)&wvpT[ci * 32 + co0];
            ull w0 = pk2(w4.x, w4.x), w1 = pk2(w4.y, w4.y);
            ull w2 = pk2(w4.z, w4.z), w3 = pk2(w4.w, w4.w);
            ffma2(acc[0][0], iA.x, w0); ffma2(acc[1][0], iA.y, w0);
            ffma2(acc[2][0], iB.x, w0); ffma2(acc[3][0], iB.y, w0);
            ffma2(acc[0][1], iA.x, w1); ffma2(acc[1][1], iA.y, w1);
            ffma2(acc[2][1], iB.x, w1); ffma2(acc[3][1], iB.y, w1);
            ffma2(acc[0][2], iA.x, w2); ffma2(acc[1][2], iA.y, w2);
            ffma2(acc[2][2], iB.x, w2); ffma2(acc[3][2], iB.y, w2);
            ffma2(acc[0][3], iA.x, w3); ffma2(acc[1][3], iA.y, w3);
            ffma2(acc[2][3], iB.x, w3); ffma2(acc[3][3], iB.y, w3);
        }
        #pragma unroll
        for (int k = 0; k < 4; k++) {
            float s = 0.0f;
            #pragma unroll
            for (int j = 0; j < 4; j++) {
                float2 f = unpk(acc[j][k]);
                int s0 = p0 + 2 * j;
                if (live && ((s0 & 15) != 15))       s += fmaxf(f.x, 0.0f);
                if (live && (((s0 + 1) & 15) != 15)) s += fmaxf(f.y, 0.0f);
            }
            s += __shfl_xor_sync(0xffffffffu, s, 8);
            s += __shfl_xor_sync(0xffffffffu, s, 16);
            if (lane < 8) atomicAdd(&vsum[lane * 4 + k], s);
        }
    }

    // ---------- P3b: policy 1x1 16->16, f32x2, S=8 C=4, tid<120 ----------
    if (tid < 120) {
        const int pgi = tid >> 2, cg = tid & 3;
        const int p0 = pgi * 8, co0 = cg * 4;
        ull acc[4][4];
        {
            float4 bv = *(const float4*)&bpp[co0];
            ull b0 = pk2(bv.x, bv.x), b1 = pk2(bv.y, bv.y);
            ull b2 = pk2(bv.z, bv.z), b3 = pk2(bv.w, bv.w);
            #pragma unroll
            for (int j = 0; j < 4; j++) {
                acc[j][0] = b0; acc[j][1] = b1; acc[j][2] = b2; acc[j][3] = b3;
            }
        }
        #pragma unroll
        for (int ci = 0; ci < 16; ci++) {
            const ulonglong2* ip = (const ulonglong2*)&conv[ci * STR2 + p0];
            ulonglong2 iA = ip[0], iB = ip[1];
            float4 w4 = *(const float4*)&wppT[ci * 16 + co0];
            ull w0 = pk2(w4.x, w4.x), w1 = pk2(w4.y, w4.y);
            ull w2 = pk2(w4.z, w4.z), w3 = pk2(w4.w, w4.w);
            ffma2(acc[0][0], iA.x, w0); ffma2(acc[1][0], iA.y, w0);
            ffma2(acc[2][0], iB.x, w0); ffma2(acc[3][0], iB.y, w0);
            ffma2(acc[0][1], iA.x, w1); ffma2(acc[1][1], iA.y, w1);
            ffma2(acc[2][1], iB.x, w1); ffma2(acc[3][1], iB.y, w1);
            ffma2(acc[0][2], iA.x, w2); ffma2(acc[1][2], iA.y, w2);
            ffma2(acc[2][2], iB.x, w2); ffma2(acc[3][2], iB.y, w2);
            ffma2(acc[0][3], iA.x, w3); ffma2(acc[1][3], iA.y, w3);
            ffma2(acc[2][3], iB.x, w3); ffma2(acc[3][3], iB.y, w3);
        }
        const bool ghost = ((p0 & 15) == 8);   // slot p0+7 is ghost
        #pragma unroll
        for (int k = 0; k < 4; k++) {
            float2 f0 = unpk(acc[0][k]), f1 = unpk(acc[1][k]);
            float2 f2 = unpk(acc[2][k]), f3 = unpk(acc[3][k]);
            float4 oA = make_float4(fmaxf(f0.x,0.f), fmaxf(f0.y,0.f),
                                    fmaxf(f1.x,0.f), fmaxf(f1.y,0.f));
            float4 oB = make_float4(fmaxf(f2.x,0.f), fmaxf(f2.y,0.f),
                                    fmaxf(f3.x,0.f), ghost ? 0.f : fmaxf(f3.y,0.f));
            float* dstc = pp + (co0 + k) * STR2 + p0;
            *(float4*)(dstc)     = oA;
            *(float4*)(dstc + 4) = oB;
        }
    }
    __syncthreads();

    // ---------- P4: policy depthwise (tid<128, row-split) | value FC (warp 7) ----------
    if (tid < 128) {
        const int c = tid >> 3, sub = tid & 7;
        const int wg = sub & 3, half = sub >> 2;
        if (half == 0)
            dwconv4<0, 8>(pp + c * STR2, pd + c * STR2, wpd + c * 9, bpd[c], wg);
        else
            dwconv4<8, 15>(pp + c * STR2, pd + c * STR2, wpd + c * 9, bpd[c], wg);
    }
    if (tid >= 224) {
        const int l = lane;
        float v = vsum[l] * (1.0f / 225.0f);
        float h1 = vl1_b[l];
        #pragma unroll
        for (int i = 0; i < 32; i++)
            h1 += vl1_w[l * 32 + i] * __shfl_sync(0xffffffffu, v, i);
        h1 = fmaxf(h1, 0.0f);
        float h2 = vl2_b[l];
        #pragma unroll
        for (int i = 0; i < 32; i++)
            h2 += vl2_w[l * 32 + i] * __shfl_sync(0xffffffffu, h1, i);
        h2 = fmaxf(h2, 0.0f);
        float o = (l < 3) ? vf_b[l] : 0.0f;
        #pragma unroll
        for (int i = 0; i < 32; i++) {
            float t = __shfl_sync(0xffffffffu, h2, i);
            if (l < 3) o += vf_w[l * 32 + i] * t;
        }
        if (l < 3) out[b * 3 + l] = o;
    }
    __syncthreads();

    // ---------- P5: pf 16->1, f32x2, tid<120 (2 slots each) ----------
    if (tid < 120) {
        const int s0 = 2 * tid;
        ull acc = 0;
        #pragma unroll
        for (int ci = 0; ci < 16; ci++) {
            ull iv = *(const ull*)&pd[ci * STR2 + s0];
            ffma2(acc, iv, pk2(wpf[ci], wpf[ci]));
        }
        float2 f = unpk(acc);
        const int w = s0 & 15, h = s0 >> 4;
        float* ob = out + BATCH * 3 + b * 225 + h * 15 + w;
        ob[0] = f.x;
        if (w < 14) ob[1] = f.y;
    }
}

extern "C" void kernel_launch(void* const* d_in, const int* in_sizes, int n_in,
                              void* d_out, int out_size) {
    (void)in_sizes; (void)n_in; (void)out_size;
    cudaFuncSetAttribute(patnet_kernel,
                         cudaFuncAttributeMaxDynamicSharedMemorySize, SMEM_BYTES);
    patnet_kernel<<<BATCH, 256, SMEM_BYTES>>>(
        (const float*)d_in[0],  (const float*)d_in[1],  (const float*)d_in[2],
        (const float*)d_in[3],  (const float*)d_in[4],  (const float*)d_in[5],
        (const float*)d_in[6],  (const float*)d_in[7],  (const float*)d_in[8],
        (const float*)d_in[9],  (const float*)d_in[10], (const float*)d_in[11],
        (const float*)d_in[12], (const float*)d_in[13], (const float*)d_in[14],
        (const float*)d_in[15], (const int*)d_in[16],   (const int*)d_in[17],
        (float*)d_out);
}

// round 8
// speedup vs baseline: 1.0988x; 1.0988x over previous
#include <cuda_runtime.h>

#define BATCH 4096
#define PC 2380
#define RW 16            // padded row width (15 cols + ghost)
#define STR2 244         // channel stride in floats (mult of 4)
#define NT 384

// ---- smem layout (float offsets) ----
#define OFF_WDW   0      // 432  conv_w 48x9
#define OFF_CB    432    // 48
#define OFF_WPD   480    // 144  pdw 16x9
#define OFF_BPD   624    // 16
#define OFF_WPF   640    // 16
#define OFF_BPP   656    // 16
#define OFF_BVP   672    // 32
#define OFF_VSUM  704    // 32
#define OFF_CODES 736    // 450 ints -> 1186
#define OFF_WPPT  1188   // 256   ppw transposed [ci][co]
#define OFF_WVPT  1444   // 1024  vpw transposed [ci][co]
#define OFF_RAW   2468   // 48*244 = 11712  (aliased: pp on rows 0..15)
#define OFF_CONV  14180  // 48*244 = 11712  (rows 0..15 aliased: pd)
#define SMEM_FLOATS 25900
#define SMEM_BYTES  (SMEM_FLOATS * 4)

typedef unsigned long long ull;

__device__ __forceinline__ void ffma2(ull& d, ull a, ull b) {
    asm("fma.rn.f32x2 %0, %1, %2, %0;" : "+l"(d) : "l"(a), "l"(b));
}
__device__ __forceinline__ ull pk2(float x, float y) {
    ull r; asm("mov.b64 %0, {%1, %2};" : "=l"(r) : "f"(x), "f"(y)); return r;
}
__device__ __forceinline__ float2 unpk(ull v) {
    float2 f; asm("mov.b64 {%0, %1}, %2;" : "=f"(f.x), "=f"(f.y) : "l"(v)); return f;
}

// depthwise 3x3, one channel, 4-col strip, output rows [H0,H1), sliding window
template<int H0, int H1>
__device__ __forceinline__ void dwconv4(const float* __restrict__ src,
                                        float* __restrict__ dst,
                                        const float* __restrict__ wk,
                                        float bias, int wg)
{
    const int w0 = wg * 4;
    const bool hasL = (wg > 0), hasR = (wg < 3);
    const float k0=wk[0],k1=wk[1],k2=wk[2],k3=wk[3],k4=wk[4],k5=wk[5],k6=wk[6],k7=wk[7],k8=wk[8];
    float al,a0,a1,a2,a3,ar, bl,b0,b1,b2,b3,br;
    if (H0 > 0) {
        const float* r = src + (H0 - 1) * RW;
        float4 m = *(const float4*)(r + w0);
        al = hasL ? r[w0 - 1] : 0.f;  ar = hasR ? r[w0 + 4] : 0.f;
        a0 = m.x; a1 = m.y; a2 = m.z; a3 = m.w;
    } else { al=a0=a1=a2=a3=ar=0.f; }
    {
        const float* r = src + H0 * RW;
        float4 m = *(const float4*)(r + w0);
        bl = hasL ? r[w0 - 1] : 0.f;  br = hasR ? r[w0 + 4] : 0.f;
        b0 = m.x; b1 = m.y; b2 = m.z; b3 = m.w;
    }
    #pragma unroll
    for (int h = H0; h < H1; h++) {
        float cl, c0, c1, c2, c3, cr;
        if (h + 1 < 15) {
            const float* r = src + (h + 1) * RW;
            float4 m = *(const float4*)(r + w0);
            cl = hasL ? r[w0 - 1] : 0.f;  cr = hasR ? r[w0 + 4] : 0.f;
            c0 = m.x; c1 = m.y; c2 = m.z; c3 = m.w;
        } else { cl = c0 = c1 = c2 = c3 = cr = 0.f; }
        float o0 = bias + al*k0+a0*k1+a1*k2 + bl*k3+b0*k4+b1*k5 + cl*k6+c0*k7+c1*k8;
        float o1 = bias + a0*k0+a1*k1+a2*k2 + b0*k3+b1*k4+b2*k5 + c0*k6+c1*k7+c2*k8;
        float o2 = bias + a1*k0+a2*k1+a3*k2 + b1*k3+b2*k4+b3*k5 + c1*k6+c2*k7+c3*k8;
        float o3 = bias + a2*k0+a3*k1+ar*k2 + b2*k3+b3*k4+br*k5 + c2*k6+c3*k7+cr*k8;
        *(float4*)(dst + h * RW + w0) =
            make_float4(fmaxf(o0,0.f), fmaxf(o1,0.f), fmaxf(o2,0.f), fmaxf(o3,0.f));
        al=bl; a0=b0; a1=b1; a2=b2; a3=b3; ar=br;
        bl=cl; b0=c0; b1=c1; b2=c2; b3=c3; br=cr;
    }
}

extern "C" __global__ void __launch_bounds__(NT, 2)
patnet_kernel(const float* __restrict__ emb,
              const float* __restrict__ conv_w, const float* __restrict__ conv_b,
              const float* __restrict__ ppw_w,  const float* __restrict__ ppw_b,
              const float* __restrict__ pdw_w,  const float* __restrict__ pdw_b,
              const float* __restrict__ pf_w,
              const float* __restrict__ vpw_w,  const float* __restrict__ vpw_b,
              const float* __restrict__ vl1_w,  const float* __restrict__ vl1_b,
              const float* __restrict__ vl2_w,  const float* __restrict__ vl2_b,
              const float* __restrict__ vf_w,   const float* __restrict__ vf_b,
              const int* __restrict__ sparse,   const int* __restrict__ board,
              float* __restrict__ out)
{
    extern __shared__ float sm[];
    float* wdw  = sm + OFF_WDW;
    float* cb   = sm + OFF_CB;
    float* wpd  = sm + OFF_WPD;
    float* bpd  = sm + OFF_BPD;
    float* wpf  = sm + OFF_WPF;
    float* bpp  = sm + OFF_BPP;
    float* bvp  = sm + OFF_BVP;
    float* vsum = sm + OFF_VSUM;
    int*   codes= (int*)(sm + OFF_CODES);
    float* wppT = sm + OFF_WPPT;
    float* wvpT = sm + OFF_WVPT;
    float* raw  = sm + OFF_RAW;
    float* conv = sm + OFF_CONV;
    float* pp   = raw;            // rows 0..15, after raw dead
    float* pd   = conv;           // rows 0..15, after pol-pw reads done

    const int tid  = threadIdx.x;
    const int b    = blockIdx.x;
    const int lane = tid & 31;

    // ---------- P0: weights -> smem, codes ----------
    for (int i = tid; i < 432; i += NT) wdw[i] = conv_w[i];
    for (int i = tid; i < 48;  i += NT) cb[i]  = conv_b[i];
    for (int i = tid; i < 144; i += NT) wpd[i] = pdw_w[i];
    if (tid < 16) { bpd[tid] = pdw_b[tid]; wpf[tid] = pf_w[tid]; bpp[tid] = ppw_b[tid]; }
    if (tid >= 32 && tid < 64) { bvp[tid-32] = vpw_b[tid-32]; vsum[tid-32] = 0.0f; }
    if (tid >= 64 && tid < 320) {
        int i = tid - 64;
        int co = i >> 4, ci = i & 15;
        wppT[ci * 16 + co] = ppw_w[i];
    }
    for (int i = tid; i < 1024; i += NT) {
        int co = i >> 5, ci = i & 31;
        wvpT[ci * 32 + co] = vpw_w[i];
    }
    for (int i = tid; i < 450; i += NT) {
        int j = i / 225, p = i - j * 225;
        int sp = sparse[b * 2700 + (10 + j) * 225 + p];
        int bd = board[b * 450 + j * 225 + p];
        int c = (bd > 0) ? PC : sp;
        codes[i] = c + j * (PC + 1);
    }
    __syncthreads();

    // ---------- P1: gather all 48 ch, register transpose, vector STS ----------
    #pragma unroll
    for (int task = 0; task < 2; task++) {
        const int t = tid + task * NT;
        if (t < 720) {
            const int cblk = t / 60, g = t - cblk * 60;
            const int h = g >> 2, w0 = (g & 3) * 4;
            const int cb4 = cblk * 4;
            float4 v[4];
            #pragma unroll
            for (int j = 0; j < 4; j++) {
                int w = w0 + j;
                if (w < 15) {
                    int p = h * 15 + w;
                    int c0 = codes[p], c1 = codes[225 + p];
                    float4 a = *(const float4*)(emb + c0 * 48 + cb4);
                    float4 bb = *(const float4*)(emb + c1 * 48 + cb4);
                    v[j] = make_float4(a.x+bb.x, a.y+bb.y, a.z+bb.z, a.w+bb.w);
                } else v[j] = make_float4(0.f, 0.f, 0.f, 0.f);
            }
            float* base = raw + h * RW + w0;
            *(float4*)(base + (cb4+0)*STR2) = make_float4(v[0].x, v[1].x, v[2].x, v[3].x);
            *(float4*)(base + (cb4+1)*STR2) = make_float4(v[0].y, v[1].y, v[2].y, v[3].y);
            *(float4*)(base + (cb4+2)*STR2) = make_float4(v[0].z, v[1].z, v[2].z, v[3].z);
            *(float4*)(base + (cb4+3)*STR2) = make_float4(v[0].w, v[1].w, v[2].w, v[3].w);
        }
    }
    __syncthreads();

    // ---------- P2: main depthwise 3x3, 48 ch x 4 strips x 2 halves = 384 ----------
    {
        const int c = tid >> 3, sub = tid & 7;
        const int wg = sub & 3, half = sub >> 2;
        if (half == 0)
            dwconv4<0, 8>(raw + c * STR2, conv + c * STR2, wdw + c * 9, cb[c], wg);
        else
            dwconv4<8, 15>(raw + c * STR2, conv + c * STR2, wdw + c * 9, cb[c], wg);
    }
    __syncthreads();

    // ---------- P3: value pw (warps 0..7) || policy pw (warps 8..11) ----------
    if (tid < 256) {
        // value 1x1 32->32, f32x2, S=8 C=4
        const int cg = tid & 7, pgi = tid >> 3;
        const bool live = (pgi < 30);
        const int p0 = live ? pgi * 8 : 0;
        const int co0 = cg * 4;
        ull acc[4][4];
        {
            float4 bv = *(const float4*)&bvp[co0];
            ull b0 = pk2(bv.x, bv.x), b1 = pk2(bv.y, bv.y);
            ull b2 = pk2(bv.z, bv.z), b3 = pk2(bv.w, bv.w);
            #pragma unroll
            for (int j = 0; j < 4; j++) {
                acc[j][0] = b0; acc[j][1] = b1; acc[j][2] = b2; acc[j][3] = b3;
            }
        }
        #pragma unroll 8
        for (int ci = 0; ci < 32; ci++) {
            const ulonglong2* ip = (const ulonglong2*)&conv[(16 + ci) * STR2 + p0];
            ulonglong2 iA = ip[0], iB = ip[1];
            float4 w4 = *(const float4*)&wvpT[ci * 32 + co0];
            ull w0 = pk2(w4.x, w4.x), w1 = pk2(w4.y, w4.y);
            ull w2 = pk2(w4.z, w4.z), w3 = pk2(w4.w, w4.w);
            ffma2(acc[0][0], iA.x, w0); ffma2(acc[1][0], iA.y, w0);
            ffma2(acc[2][0], iB.x, w0); ffma2(acc[3][0], iB.y, w0);
            ffma2(acc[0][1], iA.x, w1); ffma2(acc[1][1], iA.y, w1);
            ffma2(acc[2][1], iB.x, w1); ffma2(acc[3][1], iB.y, w1);
            ffma2(acc[0][2], iA.x, w2); ffma2(acc[1][2], iA.y, w2);
            ffma2(acc[2][2], iB.x, w2); ffma2(acc[3][2], iB.y, w2);
            ffma2(acc[0][3], iA.x, w3); ffma2(acc[1][3], iA.y, w3);
            ffma2(acc[2][3], iB.x, w3); ffma2(acc[3][3], iB.y, w3);
        }
        #pragma unroll
        for (int k = 0; k < 4; k++) {
            float s = 0.0f;
            #pragma unroll
            for (int j = 0; j < 4; j++) {
                float2 f = unpk(acc[j][k]);
                int s0 = p0 + 2 * j;
                if (live && ((s0 & 15) != 15))       s += fmaxf(f.x, 0.0f);
                if (live && (((s0 + 1) & 15) != 15)) s += fmaxf(f.y, 0.0f);
            }
            s += __shfl_xor_sync(0xffffffffu, s, 8);
            s += __shfl_xor_sync(0xffffffffu, s, 16);
            if (lane < 8) atomicAdd(&vsum[lane * 4 + k], s);
        }
    } else {
        // policy 1x1 16->16, f32x2, S=8 C=4, 120 live of 128 (30 pos-groups!)
        const int t = tid - 256;
        if (t < 120) {
            const int pgi = t >> 2, cg = t & 3;
            const int p0 = pgi * 8, co0 = cg * 4;
            ull acc[4][4];
            {
                float4 bv = *(const float4*)&bpp[co0];
                ull b0 = pk2(bv.x, bv.x), b1 = pk2(bv.y, bv.y);
                ull b2 = pk2(bv.z, bv.z), b3 = pk2(bv.w, bv.w);
                #pragma unroll
                for (int j = 0; j < 4; j++) {
                    acc[j][0] = b0; acc[j][1] = b1; acc[j][2] = b2; acc[j][3] = b3;
                }
            }
            #pragma unroll
            for (int ci = 0; ci < 16; ci++) {
                const ulonglong2* ip = (const ulonglong2*)&conv[ci * STR2 + p0];
                ulonglong2 iA = ip[0], iB = ip[1];
                float4 w4 = *(const float4*)&wppT[ci * 16 + co0];
                ull w0 = pk2(w4.x, w4.x), w1 = pk2(w4.y, w4.y);
                ull w2 = pk2(w4.z, w4.z), w3 = pk2(w4.w, w4.w);
                ffma2(acc[0][0], iA.x, w0); ffma2(acc[1][0], iA.y, w0);
                ffma2(acc[2][0], iB.x, w0); ffma2(acc[3][0], iB.y, w0);
                ffma2(acc[0][1], iA.x, w1); ffma2(acc[1][1], iA.y, w1);
                ffma2(acc[2][1], iB.x, w1); ffma2(acc[3][1], iB.y, w1);
                ffma2(acc[0][2], iA.x, w2); ffma2(acc[1][2], iA.y, w2);
                ffma2(acc[2][2], iB.x, w2); ffma2(acc[3][2], iB.y, w2);
                ffma2(acc[0][3], iA.x, w3); ffma2(acc[1][3], iA.y, w3);
                ffma2(acc[2][3], iB.x, w3); ffma2(acc[3][3], iB.y, w3);
            }
            const bool ghost = ((p0 & 15) == 8);   // slot p0+7 is ghost
            #pragma unroll
            for (int k = 0; k < 4; k++) {
                float2 f0 = unpk(acc[0][k]), f1 = unpk(acc[1][k]);
                float2 f2 = unpk(acc[2][k]), f3 = unpk(acc[3][k]);
                float4 oA = make_float4(fmaxf(f0.x,0.f), fmaxf(f0.y,0.f),
                                        fmaxf(f1.x,0.f), fmaxf(f1.y,0.f));
                float4 oB = make_float4(fmaxf(f2.x,0.f), fmaxf(f2.y,0.f),
                                        fmaxf(f3.x,0.f), ghost ? 0.f : fmaxf(f3.y,0.f));
                float* dstc = pp + (co0 + k) * STR2 + p0;
                *(float4*)(dstc)     = oA;
                *(float4*)(dstc + 4) = oB;
            }
        }
    }
    __syncthreads();

    // ---------- P4: policy depthwise (tid<128, row-split) | value FC (warp 11) ----------
    if (tid < 128) {
        const int c = tid >> 3, sub = tid & 7;
        const int wg = sub & 3, half = sub >> 2;
        if (half == 0)
            dwconv4<0, 8>(pp + c * STR2, pd + c * STR2, wpd + c * 9, bpd[c], wg);
        else
            dwconv4<8, 15>(pp + c * STR2, pd + c * STR2, wpd + c * 9, bpd[c], wg);
    }
    if (tid >= 352) {
        const int l = lane;
        float v = vsum[l] * (1.0f / 225.0f);
        float h1 = vl1_b[l];
        #pragma unroll
        for (int i = 0; i < 32; i++)
            h1 += vl1_w[l * 32 + i] * __shfl_sync(0xffffffffu, v, i);
        h1 = fmaxf(h1, 0.0f);
        float h2 = vl2_b[l];
        #pragma unroll
        for (int i = 0; i < 32; i++)
            h2 += vl2_w[l * 32 + i] * __shfl_sync(0xffffffffu, h1, i);
        h2 = fmaxf(h2, 0.0f);
        float o = (l < 3) ? vf_b[l] : 0.0f;
        #pragma unroll
        for (int i = 0; i < 32; i++) {
            float t = __shfl_sync(0xffffffffu, h2, i);
            if (l < 3) o += vf_w[l * 32 + i] * t;
        }
        if (l < 3) out[b * 3 + l] = o;
    }
    __syncthreads();

    // ---------- P5: pf 16->1, f32x2, tid<120 (2 slots each) ----------
    if (tid < 120) {
        const int s0 = 2 * tid;
        ull acc = 0;
        #pragma unroll
        for (int ci = 0; ci < 16; ci++) {
            ull iv = *(const ull*)&pd[ci * STR2 + s0];
            ffma2(acc, iv, pk2(wpf[ci], wpf[ci]));
        }
        float2 f = unpk(acc);
        const int w = s0 & 15, h = s0 >> 4;
        float* ob = out + BATCH * 3 + b * 225 + h * 15 + w;
        ob[0] = f.x;
        if (w < 14) ob[1] = f.y;
    }
}

extern "C" void kernel_launch(void* const* d_in, const int* in_sizes, int n_in,
                              void* d_out, int out_size) {
    (void)in_sizes; (void)n_in; (void)out_size;
    cudaFuncSetAttribute(patnet_kernel,
                         cudaFuncAttributeMaxDynamicSharedMemorySize, SMEM_BYTES);
    patnet_kernel<<<BATCH, NT, SMEM_BYTES>>>(
        (const float*)d_in[0],  (const float*)d_in[1],  (const float*)d_in[2],
        (const float*)d_in[3],  (const float*)d_in[4],  (const float*)d_in[5],
        (const float*)d_in[6],  (const float*)d_in[7],  (const float*)d_in[8],
        (const float*)d_in[9],  (const float*)d_in[10], (const float*)d_in[11],
        (const float*)d_in[12], (const float*)d_in[13], (const float*)d_in[14],
        (const float*)d_in[15], (const int*)d_in[16],   (const int*)d_in[17],
        (float*)d_out);
}

// round 9
// speedup vs baseline: 1.1041x; 1.0049x over previous
#include <cuda_runtime.h>

#define BATCH 4096
#define PC 2380
#define RW 16            // padded row width (15 cols + ghost)
#define STR2 260         // channel stride in floats (mult of 4, room for stagger)
#define NT 384
#define STAG(c) ((((c) >> 2) & 7) * 4)   // per-channel-quad bank stagger (floats)

// ---- smem layout (float offsets) ----
#define OFF_WDW   0      // 432  conv_w 48x9
#define OFF_CB    432    // 48
#define OFF_WPD   480    // 144  pdw 16x9
#define OFF_BPD   624    // 16
#define OFF_WPF   640    // 16
#define OFF_BPP   656    // 16
#define OFF_BVP   672    // 32
#define OFF_VSUM  704    // 32
#define OFF_CODES 736    // 450 ints -> 1186
#define OFF_WPPT  1188   // 256   ppw transposed [ci][co]
#define OFF_WVPT  1444   // 1024  vpw transposed [ci][co]
#define OFF_RAW   2468   // 48*260 = 12480  (aliased: pp on rows 0..15)
#define OFF_CONV  14948  // 48*260 = 12480  (rows 0..15 aliased: pd)
#define SMEM_FLOATS 27430
#define SMEM_BYTES  (SMEM_FLOATS * 4)

typedef unsigned long long ull;

__device__ __forceinline__ void ffma2(ull& d, ull a, ull b) {
    asm("fma.rn.f32x2 %0, %1, %2, %0;" : "+l"(d) : "l"(a), "l"(b));
}
__device__ __forceinline__ ull pk2(float x, float y) {
    ull r; asm("mov.b64 %0, {%1, %2};" : "=l"(r) : "f"(x), "f"(y)); return r;
}
__device__ __forceinline__ float2 unpk(ull v) {
    float2 f; asm("mov.b64 {%0, %1}, %2;" : "=f"(f.x), "=f"(f.y) : "l"(v)); return f;
}

// depthwise 3x3, one channel, 4-col strip, output rows [H0,H1), sliding window
template<int H0, int H1>
__device__ __forceinline__ void dwconv4(const float* __restrict__ src,
                                        float* __restrict__ dst,
                                        const float* __restrict__ wk,
                                        float bias, int wg)
{
    const int w0 = wg * 4;
    const bool hasL = (wg > 0), hasR = (wg < 3);
    const float k0=wk[0],k1=wk[1],k2=wk[2],k3=wk[3],k4=wk[4],k5=wk[5],k6=wk[6],k7=wk[7],k8=wk[8];
    float al,a0,a1,a2,a3,ar, bl,b0,b1,b2,b3,br;
    if (H0 > 0) {
        const float* r = src + (H0 - 1) * RW;
        float4 m = *(const float4*)(r + w0);
        al = hasL ? r[w0 - 1] : 0.f;  ar = hasR ? r[w0 + 4] : 0.f;
        a0 = m.x; a1 = m.y; a2 = m.z; a3 = m.w;
    } else { al=a0=a1=a2=a3=ar=0.f; }
    {
        const float* r = src + H0 * RW;
        float4 m = *(const float4*)(r + w0);
        bl = hasL ? r[w0 - 1] : 0.f;  br = hasR ? r[w0 + 4] : 0.f;
        b0 = m.x; b1 = m.y; b2 = m.z; b3 = m.w;
    }
    #pragma unroll
    for (int h = H0; h < H1; h++) {
        float cl, c0, c1, c2, c3, cr;
        if (h + 1 < 15) {
            const float* r = src + (h + 1) * RW;
            float4 m = *(const float4*)(r + w0);
            cl = hasL ? r[w0 - 1] : 0.f;  cr = hasR ? r[w0 + 4] : 0.f;
            c0 = m.x; c1 = m.y; c2 = m.z; c3 = m.w;
        } else { cl = c0 = c1 = c2 = c3 = cr = 0.f; }
        float o0 = bias + al*k0+a0*k1+a1*k2 + bl*k3+b0*k4+b1*k5 + cl*k6+c0*k7+c1*k8;
        float o1 = bias + a0*k0+a1*k1+a2*k2 + b0*k3+b1*k4+b2*k5 + c0*k6+c1*k7+c2*k8;
        float o2 = bias + a1*k0+a2*k1+a3*k2 + b1*k3+b2*k4+b3*k5 + c1*k6+c2*k7+c3*k8;
        float o3 = bias + a2*k0+a3*k1+ar*k2 + b2*k3+b3*k4+br*k5 + c2*k6+c3*k7+cr*k8;
        *(float4*)(dst + h * RW + w0) =
            make_float4(fmaxf(o0,0.f), fmaxf(o1,0.f), fmaxf(o2,0.f), fmaxf(o3,0.f));
        al=bl; a0=b0; a1=b1; a2=b2; a3=b3; ar=br;
        bl=cl; b0=c0; b1=c1; b2=c2; b3=c3; br=cr;
    }
}

extern "C" __global__ void __launch_bounds__(NT, 2)
patnet_kernel(const float* __restrict__ emb,
              const float* __restrict__ conv_w, const float* __restrict__ conv_b,
              const float* __restrict__ ppw_w,  const float* __restrict__ ppw_b,
              const float* __restrict__ pdw_w,  const float* __restrict__ pdw_b,
              const float* __restrict__ pf_w,
              const float* __restrict__ vpw_w,  const float* __restrict__ vpw_b,
              const float* __restrict__ vl1_w,  const float* __restrict__ vl1_b,
              const float* __restrict__ vl2_w,  const float* __restrict__ vl2_b,
              const float* __restrict__ vf_w,   const float* __restrict__ vf_b,
              const int* __restrict__ sparse,   const int* __restrict__ board,
              float* __restrict__ out)
{
    extern __shared__ float sm[];
    float* wdw  = sm + OFF_WDW;
    float* cb   = sm + OFF_CB;
    float* wpd  = sm + OFF_WPD;
    float* bpd  = sm + OFF_BPD;
    float* wpf  = sm + OFF_WPF;
    float* bpp  = sm + OFF_BPP;
    float* bvp  = sm + OFF_BVP;
    float* vsum = sm + OFF_VSUM;
    int*   codes= (int*)(sm + OFF_CODES);
    float* wppT = sm + OFF_WPPT;
    float* wvpT = sm + OFF_WVPT;
    float* raw  = sm + OFF_RAW;
    float* conv = sm + OFF_CONV;
    float* pp   = raw;            // rows 0..15, after raw dead
    float* pd   = conv;           // rows 0..15, after pol-pw reads done

    const int tid  = threadIdx.x;
    const int b    = blockIdx.x;
    const int lane = tid & 31;

    // ---------- P0: weights -> smem, codes, ghost zeroing ----------
    for (int i = tid; i < 432; i += NT) wdw[i] = conv_w[i];
    for (int i = tid; i < 48;  i += NT) cb[i]  = conv_b[i];
    for (int i = tid; i < 144; i += NT) wpd[i] = pdw_w[i];
    if (tid < 16) { bpd[tid] = pdw_b[tid]; wpf[tid] = pf_w[tid]; bpp[tid] = ppw_b[tid]; }
    if (tid >= 32 && tid < 64) { bvp[tid-32] = vpw_b[tid-32]; vsum[tid-32] = 0.0f; }
    if (tid >= 64 && tid < 320) {
        int i = tid - 64;
        int co = i >> 4, ci = i & 15;
        wppT[ci * 16 + co] = ppw_w[i];
    }
    for (int i = tid; i < 1024; i += NT) {
        int co = i >> 5, ci = i & 31;
        wvpT[ci * 32 + co] = vpw_w[i];
    }
    for (int i = tid; i < 720; i += NT) {   // zero ghost col (w=15) of raw, 48ch x 15h
        int c = i / 15, h = i - c * 15;
        raw[c * STR2 + STAG(c) + h * RW + 15] = 0.0f;
    }
    for (int i = tid; i < 450; i += NT) {
        int j = i / 225, p = i - j * 225;
        int sp = sparse[b * 2700 + (10 + j) * 225 + p];
        int bd = board[b * 450 + j * 225 + p];
        int c = (bd > 0) ? PC : sp;
        codes[i] = c + j * (PC + 1);
    }
    __syncthreads();

    // ---------- P1: cooperative gather, 2 positions/warp, no shuffles ----------
    {
        const int warpid = tid >> 5;
        const int g = lane >> 4;          // position sub-group 0/1
        const int q = lane & 15;          // channel-quad index (active q<12)
        #pragma unroll 1
        for (int it = 0; it < 10; it++) {
            const int p = it * 24 + warpid * 2 + g;
            if (p < 225 && q < 12) {
                const int c0 = codes[p], c1 = codes[225 + p];
                float4 a  = *(const float4*)(emb + c0 * 48 + q * 4);
                float4 bb = *(const float4*)(emb + c1 * 48 + q * 4);
                const int h = p / 15, w = p - h * 15;
                const int slot = h * RW + w;
                float* dst = raw + (q * 4) * STR2 + ((q & 7) << 2) + slot;
                dst[0]        = a.x + bb.x;
                dst[STR2]     = a.y + bb.y;
                dst[2 * STR2] = a.z + bb.z;
                dst[3 * STR2] = a.w + bb.w;
            }
        }
    }
    __syncthreads();

    // ---------- P2: main depthwise 3x3, 48 ch x 4 strips x 2 halves = 384 ----------
    {
        const int c = tid >> 3, sub = tid & 7;
        const int wg = sub & 3, half = sub >> 2;
        const int off = c * STR2 + STAG(c);
        if (half == 0)
            dwconv4<0, 8>(raw + off, conv + off, wdw + c * 9, cb[c], wg);
        else
            dwconv4<8, 15>(raw + off, conv + off, wdw + c * 9, cb[c], wg);
    }
    __syncthreads();

    // ---------- P3: value pw (warps 0..7) || policy pw (warps 8..11) ----------
    if (tid < 256) {
        // value 1x1 32->32, f32x2, S=8 C=4
        const int cg = tid & 7, pgi = tid >> 3;
        const bool live = (pgi < 30);
        const int p0 = live ? pgi * 8 : 0;
        const int co0 = cg * 4;
        ull acc[4][4];
        {
            float4 bv = *(const float4*)&bvp[co0];
            ull b0 = pk2(bv.x, bv.x), b1 = pk2(bv.y, bv.y);
            ull b2 = pk2(bv.z, bv.z), b3 = pk2(bv.w, bv.w);
            #pragma unroll
            for (int j = 0; j < 4; j++) {
                acc[j][0] = b0; acc[j][1] = b1; acc[j][2] = b2; acc[j][3] = b3;
            }
        }
        #pragma unroll 8
        for (int ci = 0; ci < 32; ci++) {
            const int c = 16 + ci;
            const ulonglong2* ip = (const ulonglong2*)&conv[c * STR2 + STAG(c) + p0];
            ulonglong2 iA = ip[0], iB = ip[1];
            float4 w4 = *(const float4*)&wvpT[ci * 32 + co0];
            ull w0 = pk2(w4.x, w4.x), w1 = pk2(w4.y, w4.y);
            ull w2 = pk2(w4.z, w4.z), w3 = pk2(w4.w, w4.w);
            ffma2(acc[0][0], iA.x, w0); ffma2(acc[1][0], iA.y, w0);
            ffma2(acc[2][0], iB.x, w0); ffma2(acc[3][0], iB.y, w0);
            ffma2(acc[0][1], iA.x, w1); ffma2(acc[1][1], iA.y, w1);
            ffma2(acc[2][1], iB.x, w1); ffma2(acc[3][1], iB.y, w1);
            ffma2(acc[0][2], iA.x, w2); ffma2(acc[1][2], iA.y, w2);
            ffma2(acc[2][2], iB.x, w2); ffma2(acc[3][2], iB.y, w2);
            ffma2(acc[0][3], iA.x, w3); ffma2(acc[1][3], iA.y, w3);
            ffma2(acc[2][3], iB.x, w3); ffma2(acc[3][3], iB.y, w3);
        }
        #pragma unroll
        for (int k = 0; k < 4; k++) {
            float s = 0.0f;
            #pragma unroll
            for (int j = 0; j < 4; j++) {
                float2 f = unpk(acc[j][k]);
                int s0 = p0 + 2 * j;
                if (live && ((s0 & 15) != 15))       s += fmaxf(f.x, 0.0f);
                if (live && (((s0 + 1) & 15) != 15)) s += fmaxf(f.y, 0.0f);
            }
            s += __shfl_xor_sync(0xffffffffu, s, 8);
            s += __shfl_xor_sync(0xffffffffu, s, 16);
            if (lane < 8) atomicAdd(&vsum[lane * 4 + k], s);
        }
    } else {
        // policy 1x1 16->16, f32x2, S=8 C=4, 120 live (30 pos-groups x 4 co-groups)
        const int t = tid - 256;
        if (t < 120) {
            const int pgi = t >> 2, cg = t & 3;
            const int p0 = pgi * 8, co0 = cg * 4;
            ull acc[4][4];
            {
                float4 bv = *(const float4*)&bpp[co0];
                ull b0 = pk2(bv.x, bv.x), b1 = pk2(bv.y, bv.y);
                ull b2 = pk2(bv.z, bv.z), b3 = pk2(bv.w, bv.w);
                #pragma unroll
                for (int j = 0; j < 4; j++) {
                    acc[j][0] = b0; acc[j][1] = b1; acc[j][2] = b2; acc[j][3] = b3;
                }
            }
            #pragma unroll
            for (int ci = 0; ci < 16; ci++) {
                const ulonglong2* ip = (const ulonglong2*)&conv[ci * STR2 + STAG(ci) + p0];
                ulonglong2 iA = ip[0], iB = ip[1];
                float4 w4 = *(const float4*)&wppT[ci * 16 + co0];
                ull w0 = pk2(w4.x, w4.x), w1 = pk2(w4.y, w4.y);
                ull w2 = pk2(w4.z, w4.z), w3 = pk2(w4.w, w4.w);
                ffma2(acc[0][0], iA.x, w0); ffma2(acc[1][0], iA.y, w0);
                ffma2(acc[2][0], iB.x, w0); ffma2(acc[3][0], iB.y, w0);
                ffma2(acc[0][1], iA.x, w1); ffma2(acc[1][1], iA.y, w1);
                ffma2(acc[2][1], iB.x, w1); ffma2(acc[3][1], iB.y, w1);
                ffma2(acc[0][2], iA.x, w2); ffma2(acc[1][2], iA.y, w2);
                ffma2(acc[2][2], iB.x, w2); ffma2(acc[3][2], iB.y, w2);
                ffma2(acc[0][3], iA.x, w3); ffma2(acc[1][3], iA.y, w3);
                ffma2(acc[2][3], iB.x, w3); ffma2(acc[3][3], iB.y, w3);
            }
            const bool ghost = ((p0 & 15) == 8);   // slot p0+7 is ghost
            #pragma unroll
            for (int k = 0; k < 4; k++) {
                float2 f0 = unpk(acc[0][k]), f1 = unpk(acc[1][k]);
                float2 f2 = unpk(acc[2][k]), f3 = unpk(acc[3][k]);
                float4 oA = make_float4(fmaxf(f0.x,0.f), fmaxf(f0.y,0.f),
                                        fmaxf(f1.x,0.f), fmaxf(f1.y,0.f));
                float4 oB = make_float4(fmaxf(f2.x,0.f), fmaxf(f2.y,0.f),
                                        fmaxf(f3.x,0.f), ghost ? 0.f : fmaxf(f3.y,0.f));
                const int co = co0 + k;
                float* dstc = pp + co * STR2 + STAG(co) + p0;
                *(float4*)(dstc)     = oA;
                *(float4*)(dstc + 4) = oB;
            }
        }
    }
    __syncthreads();

    // ---------- P4: policy depthwise (tid<128, row-split) | value FC (warp 11) ----------
    if (tid < 128) {
        const int c = tid >> 3, sub = tid & 7;
        const int wg = sub & 3, half = sub >> 2;
        const int off = c * STR2 + STAG(c);
        if (half == 0)
            dwconv4<0, 8>(pp + off, pd + off, wpd + c * 9, bpd[c], wg);
        else
            dwconv4<8, 15>(pp + off, pd + off, wpd + c * 9, bpd[c], wg);
    }
    if (tid >= 352) {
        const int l = lane;
        float v = vsum[l] * (1.0f / 225.0f);
        float h1 = vl1_b[l];
        #pragma unroll
        for (int i = 0; i < 32; i++)
            h1 += vl1_w[l * 32 + i] * __shfl_sync(0xffffffffu, v, i);
        h1 = fmaxf(h1, 0.0f);
        float h2 = vl2_b[l];
        #pragma unroll
        for (int i = 0; i < 32; i++)
            h2 += vl2_w[l * 32 + i] * __shfl_sync(0xffffffffu, h1, i);
        h2 = fmaxf(h2, 0.0f);
        float o = (l < 3) ? vf_b[l] : 0.0f;
        #pragma unroll
        for (int i = 0; i < 32; i++) {
            float t = __shfl_sync(0xffffffffu, h2, i);
            if (l < 3) o += vf_w[l * 32 + i] * t;
        }
        if (l < 3) out[b * 3 + l] = o;
    }
    __syncthreads();

    // ---------- P5: pf 16->1, f32x2, tid<120 (2 slots each) ----------
    if (tid < 120) {
        const int s0 = 2 * tid;
        ull acc = 0;
        #pragma unroll
        for (int ci = 0; ci < 16; ci++) {
            ull iv = *(const ull*)&pd[ci * STR2 + STAG(ci) + s0];
            ffma2(acc, iv, pk2(wpf[ci], wpf[ci]));
        }
        float2 f = unpk(acc);
        const int w = s0 & 15, h = s0 >> 4;
        float* ob = out + BATCH * 3 + b * 225 + h * 15 + w;
        ob[0] = f.x;
        if (w < 14) ob[1] = f.y;
    }
}

extern "C" void kernel_launch(void* const* d_in, const int* in_sizes, int n_in,
                              void* d_out, int out_size) {
    (void)in_sizes; (void)n_in; (void)out_size;
    cudaFuncSetAttribute(patnet_kernel,
                         cudaFuncAttributeMaxDynamicSharedMemorySize, SMEM_BYTES);
    patnet_kernel<<<BATCH, NT, SMEM_BYTES>>>(
        (const float*)d_in[0],  (const float*)d_in[1],  (const float*)d_in[2],
        (const float*)d_in[3],  (const float*)d_in[4],  (const float*)d_in[5],
        (const float*)d_in[6],  (const float*)d_in[7],  (const float*)d_in[8],
        (const float*)d_in[9],  (const float*)d_in[10], (const float*)d_in[11],
        (const float*)d_in[12], (const float*)d_in[13], (const float*)d_in[14],
        (const float*)d_in[15], (const int*)d_in[16],   (const int*)d_in[17],
        (float*)d_out);
}

// round 10
// speedup vs baseline: 1.2946x; 1.1725x over previous
#include <cuda_runtime.h>

#define BATCH 4096
#define PC 2380
#define RW 16            // padded row width (15 cols + ghost)
#define STR2 244         // channel stride in floats (mult of 4)

// ---- smem layout (float offsets) ----
#define OFF_WDW   0      // 432  conv_w 48x9
#define OFF_CB    432    // 48
#define OFF_WPD   480    // 144  pdw 16x9
#define OFF_BPD   624    // 16
#define OFF_WPF   640    // 16
#define OFF_BPP   656    // 16
#define OFF_BVP   672    // 32
#define OFF_VSUM  704    // 32
#define OFF_CODES 736    // 450 ints -> 1186
#define OFF_WPPT  1188   // 256   ppw transposed [ci][co]
#define OFF_WVPT  1444   // 1024  vpw transposed [ci][co]
#define OFF_RAW   2468   // 48*244 = 11712 ; depthwise runs IN PLACE (conv==raw)
#define OFF_PP    14180  // 16*244 = 3904  ; policy pointwise output
#define SMEM_FLOATS 18084
#define SMEM_BYTES  (SMEM_FLOATS * 4)

typedef unsigned long long ull;

__device__ __forceinline__ void ffma2(ull& d, ull a, ull b) {
    asm("fma.rn.f32x2 %0, %1, %2, %0;" : "+l"(d) : "l"(a), "l"(b));
}
__device__ __forceinline__ ull pk2(float x, float y) {
    ull r; asm("mov.b64 %0, {%1, %2};" : "=l"(r) : "f"(x), "f"(y)); return r;
}
__device__ __forceinline__ float2 unpk(ull v) {
    float2 f; asm("mov.b64 {%0, %1}, %2;" : "=f"(f.x), "=f"(f.y) : "l"(v)); return f;
}

// depthwise 3x3, one channel, 4-col strip, rows [H0,H1), sliding register window.
// RESTRICT=false allows src==dst (in-place): each iteration loads row h+1 before
// storing row h; with all 4 strips of a channel in one warp, program order makes
// the in-place update safe.
template<int H0, int H1, bool RESTRICT>
__device__ __forceinline__ void dwconv4(const float* src, float* dst,
                                        const float* __restrict__ wk,
                                        float bias, int wg)
{
    const int w0 = wg * 4;
    const bool hasL = (wg > 0), hasR = (wg < 3);
    const float k0=wk[0],k1=wk[1],k2=wk[2],k3=wk[3],k4=wk[4],k5=wk[5],k6=wk[6],k7=wk[7],k8=wk[8];
    float al,a0,a1,a2,a3,ar, bl,b0,b1,b2,b3,br;
    if (H0 > 0) {
        const float* r = src + (H0 - 1) * RW;
        float4 m = *(const float4*)(r + w0);
        al = hasL ? r[w0 - 1] : 0.f;  ar = hasR ? r[w0 + 4] : 0.f;
        a0 = m.x; a1 = m.y; a2 = m.z; a3 = m.w;
    } else { al=a0=a1=a2=a3=ar=0.f; }
    {
        const float* r = src + H0 * RW;
        float4 m = *(const float4*)(r + w0);
        bl = hasL ? r[w0 - 1] : 0.f;  br = hasR ? r[w0 + 4] : 0.f;
        b0 = m.x; b1 = m.y; b2 = m.z; b3 = m.w;
    }
    #pragma unroll
    for (int h = H0; h < H1; h++) {
        float cl, c0, c1, c2, c3, cr;
        if (h + 1 < 15) {
            const float* r = src + (h + 1) * RW;
            float4 m = *(const float4*)(r + w0);
            cl = hasL ? r[w0 - 1] : 0.f;  cr = hasR ? r[w0 + 4] : 0.f;
            c0 = m.x; c1 = m.y; c2 = m.z; c3 = m.w;
        } else { cl = c0 = c1 = c2 = c3 = cr = 0.f; }
        float o0 = bias + al*k0+a0*k1+a1*k2 + bl*k3+b0*k4+b1*k5 + cl*k6+c0*k7+c1*k8;
        float o1 = bias + a0*k0+a1*k1+a2*k2 + b0*k3+b1*k4+b2*k5 + c0*k6+c1*k7+c2*k8;
        float o2 = bias + a1*k0+a2*k1+a3*k2 + b1*k3+b2*k4+b3*k5 + c1*k6+c2*k7+c3*k8;
        float o3 = bias + a2*k0+a3*k1+ar*k2 + b2*k3+b3*k4+br*k5 + c2*k6+c3*k7+cr*k8;
        *(float4*)(dst + h * RW + w0) =
            make_float4(fmaxf(o0,0.f), fmaxf(o1,0.f), fmaxf(o2,0.f), fmaxf(o3,0.f));
        al=bl; a0=b0; a1=b1; a2=b2; a3=b3; ar=br;
        bl=cl; b0=c0; b1=c1; b2=c2; b3=c3; br=cr;
    }
}

extern "C" __global__ void __launch_bounds__(256, 3)
patnet_kernel(const float* __restrict__ emb,
              const float* __restrict__ conv_w, const float* __restrict__ conv_b,
              const float* __restrict__ ppw_w,  const float* __restrict__ ppw_b,
              const float* __restrict__ pdw_w,  const float* __restrict__ pdw_b,
              const float* __restrict__ pf_w,
              const float* __restrict__ vpw_w,  const float* __restrict__ vpw_b,
              const float* __restrict__ vl1_w,  const float* __restrict__ vl1_b,
              const float* __restrict__ vl2_w,  const float* __restrict__ vl2_b,
              const float* __restrict__ vf_w,   const float* __restrict__ vf_b,
              const int* __restrict__ sparse,   const int* __restrict__ board,
              float* __restrict__ out)
{
    extern __shared__ float sm[];
    float* wdw  = sm + OFF_WDW;
    float* cb   = sm + OFF_CB;
    float* wpd  = sm + OFF_WPD;
    float* bpd  = sm + OFF_BPD;
    float* wpf  = sm + OFF_WPF;
    float* bpp  = sm + OFF_BPP;
    float* bvp  = sm + OFF_BVP;
    float* vsum = sm + OFF_VSUM;
    int*   codes= (int*)(sm + OFF_CODES);
    float* wppT = sm + OFF_WPPT;
    float* wvpT = sm + OFF_WVPT;
    float* raw  = sm + OFF_RAW;
    float* conv = raw;                 // depthwise is IN PLACE
    float* pp   = sm + OFF_PP;
    float* pd   = raw + 16 * STR2;     // value rows dead after P3a

    const int tid = threadIdx.x;
    const int b   = blockIdx.x;
    const int lane = tid & 31;

    // ---------- P0: weights -> smem, codes ----------
    for (int i = tid; i < 432; i += 256) wdw[i] = conv_w[i];
    for (int i = tid; i < 48;  i += 256) cb[i]  = conv_b[i];
    for (int i = tid; i < 144; i += 256) wpd[i] = pdw_w[i];
    if (tid < 16) { bpd[tid] = pdw_b[tid]; wpf[tid] = pf_w[tid]; bpp[tid] = ppw_b[tid]; }
    if (tid >= 32 && tid < 64) { bvp[tid-32] = vpw_b[tid-32]; vsum[tid-32] = 0.0f; }
    for (int i = tid; i < 256; i += 256) {
        int co = i >> 4, ci = i & 15;
        wppT[ci * 16 + co] = ppw_w[i];
    }
    for (int i = tid; i < 1024; i += 256) {
        int co = i >> 5, ci = i & 31;
        wvpT[ci * 32 + co] = vpw_w[i];
    }
    for (int i = tid; i < 450; i += 256) {
        int j = i / 225, p = i - j * 225;
        int sp = sparse[b * 2700 + (10 + j) * 225 + p];
        int bd = board[b * 450 + j * 225 + p];
        int c = (bd > 0) ? PC : sp;
        codes[i] = c + j * (PC + 1);
    }
    __syncthreads();

    // ---------- P1: gather all 48 ch, register transpose, vector STS ----------
    if (tid < 240) {
        #pragma unroll
        for (int task = 0; task < 3; task++) {
            const int t = tid + task * 240;
            const int cblk = t / 60, g = t - cblk * 60;
            const int h = g >> 2, w0 = (g & 3) * 4;
            const int cb4 = cblk * 4;
            float4 v[4];
            #pragma unroll
            for (int j = 0; j < 4; j++) {
                int w = w0 + j;
                if (w < 15) {
                    int p = h * 15 + w;
                    int c0 = codes[p], c1 = codes[225 + p];
                    float4 a = *(const float4*)(emb + c0 * 48 + cb4);
                    float4 bb = *(const float4*)(emb + c1 * 48 + cb4);
                    v[j] = make_float4(a.x+bb.x, a.y+bb.y, a.z+bb.z, a.w+bb.w);
                } else v[j] = make_float4(0.f, 0.f, 0.f, 0.f);
            }
            float* base = raw + h * RW + w0;
            *(float4*)(base + (cb4+0)*STR2) = make_float4(v[0].x, v[1].x, v[2].x, v[3].x);
            *(float4*)(base + (cb4+1)*STR2) = make_float4(v[0].y, v[1].y, v[2].y, v[3].y);
            *(float4*)(base + (cb4+2)*STR2) = make_float4(v[0].z, v[1].z, v[2].z, v[3].z);
            *(float4*)(base + (cb4+3)*STR2) = make_float4(v[0].w, v[1].w, v[2].w, v[3].w);
        }
    }
    __syncthreads();

    // ---------- P2: main depthwise 3x3, 48 ch, 192 threads, IN PLACE ----------
    if (tid < 192) {
        const int c = tid >> 2, wg = tid & 3;
        dwconv4<0, 15, false>(raw + c * STR2, conv + c * STR2, wdw + c * 9, cb[c], wg);
    }
    __syncthreads();

    // ---------- P3a: value 1x1 32->32, f32x2, S=8 C=4, all 256 threads ----------
    {
        const int cg = tid & 7, pgi = tid >> 3;
        const bool live = (pgi < 30);
        const int p0 = live ? pgi * 8 : 0;
        const int co0 = cg * 4;
        ull acc[4][4];
        {
            float4 bv = *(const float4*)&bvp[co0];
            ull b0 = pk2(bv.x, bv.x), b1 = pk2(bv.y, bv.y);
            ull b2 = pk2(bv.z, bv.z), b3 = pk2(bv.w, bv.w);
            #pragma unroll
            for (int j = 0; j < 4; j++) {
                acc[j][0] = b0; acc[j][1] = b1; acc[j][2] = b2; acc[j][3] = b3;
            }
        }
        #pragma unroll 8
        for (int ci = 0; ci < 32; ci++) {
            const ulonglong2* ip = (const ulonglong2*)&conv[(16 + ci) * STR2 + p0];
            ulonglong2 iA = ip[0], iB = ip[1];
            float4 w4 = *(const float4*)&wvpT[ci * 32 + co0];
            ull w0 = pk2(w4.x, w4.x), w1 = pk2(w4.y, w4.y);
            ull w2 = pk2(w4.z, w4.z), w3 = pk2(w4.w, w4.w);
            ffma2(acc[0][0], iA.x, w0); ffma2(acc[1][0], iA.y, w0);
            ffma2(acc[2][0], iB.x, w0); ffma2(acc[3][0], iB.y, w0);
            ffma2(acc[0][1], iA.x, w1); ffma2(acc[1][1], iA.y, w1);
            ffma2(acc[2][1], iB.x, w1); ffma2(acc[3][1], iB.y, w1);
            ffma2(acc[0][2], iA.x, w2); ffma2(acc[1][2], iA.y, w2);
            ffma2(acc[2][2], iB.x, w2); ffma2(acc[3][2], iB.y, w2);
            ffma2(acc[0][3], iA.x, w3); ffma2(acc[1][3], iA.y, w3);
            ffma2(acc[2][3], iB.x, w3); ffma2(acc[3][3], iB.y, w3);
        }
        #pragma unroll
        for (int k = 0; k < 4; k++) {
            float s = 0.0f;
            #pragma unroll
            for (int j = 0; j < 4; j++) {
                float2 f = unpk(acc[j][k]);
                int s0 = p0 + 2 * j;
                if (live && ((s0 & 15) != 15))       s += fmaxf(f.x, 0.0f);
                if (live && (((s0 + 1) & 15) != 15)) s += fmaxf(f.y, 0.0f);
            }
            s += __shfl_xor_sync(0xffffffffu, s, 8);
            s += __shfl_xor_sync(0xffffffffu, s, 16);
            if (lane < 8) atomicAdd(&vsum[lane * 4 + k], s);
        }
    }

    // ---------- P3b: policy 1x1 16->16, f32x2, S=8 C=4, tid<120 ----------
    if (tid < 120) {
        const int pgi = tid >> 2, cg = tid & 3;
        const int p0 = pgi * 8, co0 = cg * 4;
        ull acc[4][4];
        {
            float4 bv = *(const float4*)&bpp[co0];
            ull b0 = pk2(bv.x, bv.x), b1 = pk2(bv.y, bv.y);
            ull b2 = pk2(bv.z, bv.z), b3 = pk2(bv.w, bv.w);
            #pragma unroll
            for (int j = 0; j < 4; j++) {
                acc[j][0] = b0; acc[j][1] = b1; acc[j][2] = b2; acc[j][3] = b3;
            }
        }
        #pragma unroll
        for (int ci = 0; ci < 16; ci++) {
            const ulonglong2* ip = (const ulonglong2*)&conv[ci * STR2 + p0];
            ulonglong2 iA = ip[0], iB = ip[1];
            float4 w4 = *(const float4*)&wppT[ci * 16 + co0];
            ull w0 = pk2(w4.x, w4.x), w1 = pk2(w4.y, w4.y);
            ull w2 = pk2(w4.z, w4.z), w3 = pk2(w4.w, w4.w);
            ffma2(acc[0][0], iA.x, w0); ffma2(acc[1][0], iA.y, w0);
            ffma2(acc[2][0], iB.x, w0); ffma2(acc[3][0], iB.y, w0);
            ffma2(acc[0][1], iA.x, w1); ffma2(acc[1][1], iA.y, w1);
            ffma2(acc[2][1], iB.x, w1); ffma2(acc[3][1], iB.y, w1);
            ffma2(acc[0][2], iA.x, w2); ffma2(acc[1][2], iA.y, w2);
            ffma2(acc[2][2], iB.x, w2); ffma2(acc[3][2], iB.y, w2);
            ffma2(acc[0][3], iA.x, w3); ffma2(acc[1][3], iA.y, w3);
            ffma2(acc[2][3], iB.x, w3); ffma2(acc[3][3], iB.y, w3);
        }
        const bool ghost = ((p0 & 15) == 8);   // slot p0+7 is ghost
        #pragma unroll
        for (int k = 0; k < 4; k++) {
            float2 f0 = unpk(acc[0][k]), f1 = unpk(acc[1][k]);
            float2 f2 = unpk(acc[2][k]), f3 = unpk(acc[3][k]);
            float4 oA = make_float4(fmaxf(f0.x,0.f), fmaxf(f0.y,0.f),
                                    fmaxf(f1.x,0.f), fmaxf(f1.y,0.f));
            float4 oB = make_float4(fmaxf(f2.x,0.f), fmaxf(f2.y,0.f),
                                    fmaxf(f3.x,0.f), ghost ? 0.f : fmaxf(f3.y,0.f));
            float* dstc = pp + (co0 + k) * STR2 + p0;
            *(float4*)(dstc)     = oA;
            *(float4*)(dstc + 4) = oB;
        }
    }
    __syncthreads();

    // ---------- P4: policy depthwise (tid<128, row-split) | value FC (warp 7) ----------
    if (tid < 128) {
        const int c = tid >> 3, sub = tid & 7;
        const int wg = sub & 3, half = sub >> 2;
        if (half == 0)
            dwconv4<0, 8, true>(pp + c * STR2, pd + c * STR2, wpd + c * 9, bpd[c], wg);
        else
            dwconv4<8, 15, true>(pp + c * STR2, pd + c * STR2, wpd + c * 9, bpd[c], wg);
    }
    if (tid >= 224) {
        const int l = lane;
        float v = vsum[l] * (1.0f / 225.0f);
        float h1 = vl1_b[l];
        #pragma unroll
        for (int i = 0; i < 32; i++)
            h1 += vl1_w[l * 32 + i] * __shfl_sync(0xffffffffu, v, i);
        h1 = fmaxf(h1, 0.0f);
        float h2 = vl2_b[l];
        #pragma unroll
        for (int i = 0; i < 32; i++)
            h2 += vl2_w[l * 32 + i] * __shfl_sync(0xffffffffu, h1, i);
        h2 = fmaxf(h2, 0.0f);
        float o = (l < 3) ? vf_b[l] : 0.0f;
        #pragma unroll
        for (int i = 0; i < 32; i++) {
            float t = __shfl_sync(0xffffffffu, h2, i);
            if (l < 3) o += vf_w[l * 32 + i] * t;
        }
        if (l < 3) out[b * 3 + l] = o;
    }
    __syncthreads();

    // ---------- P5: pf 16->1, f32x2, tid<120 (2 slots each) ----------
    if (tid < 120) {
        const int s0 = 2 * tid;
        ull acc = 0;
        #pragma unroll
        for (int ci = 0; ci < 16; ci++) {
            ull iv = *(const ull*)&pd[ci * STR2 + s0];
            ffma2(acc, iv, pk2(wpf[ci], wpf[ci]));
        }
        float2 f = unpk(acc);
        const int w = s0 & 15, h = s0 >> 4;
        float* ob = out + BATCH * 3 + b * 225 + h * 15 + w;
        ob[0] = f.x;
        if (w < 14) ob[1] = f.y;
    }
}

extern "C" void kernel_launch(void* const* d_in, const int* in_sizes, int n_in,
                              void* d_out, int out_size) {
    (void)in_sizes; (void)n_in; (void)out_size;
    cudaFuncSetAttribute(patnet_kernel,
                         cudaFuncAttributeMaxDynamicSharedMemorySize, SMEM_BYTES);
    patnet_kernel<<<BATCH, 256, SMEM_BYTES>>>(
        (const float*)d_in[0],  (const float*)d_in[1],  (const float*)d_in[2],
        (const float*)d_in[3],  (const float*)d_in[4],  (const float*)d_in[5],
        (const float*)d_in[6],  (const float*)d_in[7],  (const float*)d_in[8],
        (const float*)d_in[9],  (const float*)d_in[10], (const float*)d_in[11],
        (const float*)d_in[12], (const float*)d_in[13], (const float*)d_in[14],
        (const float*)d_in[15], (const int*)d_in[16],   (const int*)d_in[17],
        (float*)d_out);
}

// round 11
// speedup vs baseline: 1.3500x; 1.0428x over previous
#include <cuda_runtime.h>

#define BATCH 4096
#define PC 2380
#define RW 16            // padded row width (15 cols + ghost)
#define STR2 244         // channel stride in floats (mult of 4)

// ---- smem layout (float offsets) ----
#define OFF_WDW   0      // 432  conv_w 48x9
#define OFF_CB    432    // 48
#define OFF_WPD   480    // 144  pdw 16x9
#define OFF_BPD   624    // 16
#define OFF_WPF   640    // 16
#define OFF_BPP   656    // 16
#define OFF_BVP   672    // 32
#define OFF_VSUM  704    // 32
#define OFF_CODES 736    // 450 ints -> 1186
#define OFF_WPPT  1188   // 256   ppw transposed [ci][co]
#define OFF_WVPT  1444   // 1024  vpw transposed [ci][co]
#define OFF_RAW   2468   // 48*244 = 11712 ; depthwise IN PLACE; pol-pw IN PLACE rows 0..15
#define SMEM_FLOATS 14180
#define SMEM_BYTES  (SMEM_FLOATS * 4)

typedef unsigned long long ull;

__device__ __forceinline__ void ffma2(ull& d, ull a, ull b) {
    asm("fma.rn.f32x2 %0, %1, %2, %0;" : "+l"(d) : "l"(a), "l"(b));
}
__device__ __forceinline__ ull pk2(float x, float y) {
    ull r; asm("mov.b64 %0, {%1, %2};" : "=l"(r) : "f"(x), "f"(y)); return r;
}
__device__ __forceinline__ float2 unpk(ull v) {
    float2 f; asm("mov.b64 {%0, %1}, %2;" : "=f"(f.x), "=f"(f.y) : "l"(v)); return f;
}

// depthwise 3x3, one channel, 4-col strip, rows [H0,H1), sliding register window.
// Safe in-place (src==dst): row h+1 is loaded before row h is stored, and all 4
// strips of a channel sit in one warp (lockstep program order).
template<int H0, int H1>
__device__ __forceinline__ void dwconv4(const float* src, float* dst,
                                        const float* __restrict__ wk,
                                        float bias, int wg)
{
    const int w0 = wg * 4;
    const bool hasL = (wg > 0), hasR = (wg < 3);
    const float k0=wk[0],k1=wk[1],k2=wk[2],k3=wk[3],k4=wk[4],k5=wk[5],k6=wk[6],k7=wk[7],k8=wk[8];
    float al,a0,a1,a2,a3,ar, bl,b0,b1,b2,b3,br;
    if (H0 > 0) {
        const float* r = src + (H0 - 1) * RW;
        float4 m = *(const float4*)(r + w0);
        al = hasL ? r[w0 - 1] : 0.f;  ar = hasR ? r[w0 + 4] : 0.f;
        a0 = m.x; a1 = m.y; a2 = m.z; a3 = m.w;
    } else { al=a0=a1=a2=a3=ar=0.f; }
    {
        const float* r = src + H0 * RW;
        float4 m = *(const float4*)(r + w0);
        bl = hasL ? r[w0 - 1] : 0.f;  br = hasR ? r[w0 + 4] : 0.f;
        b0 = m.x; b1 = m.y; b2 = m.z; b3 = m.w;
    }
    #pragma unroll
    for (int h = H0; h < H1; h++) {
        float cl, c0, c1, c2, c3, cr;
        if (h + 1 < 15) {
            const float* r = src + (h + 1) * RW;
            float4 m = *(const float4*)(r + w0);
            cl = hasL ? r[w0 - 1] : 0.f;  cr = hasR ? r[w0 + 4] : 0.f;
            c0 = m.x; c1 = m.y; c2 = m.z; c3 = m.w;
        } else { cl = c0 = c1 = c2 = c3 = cr = 0.f; }
        float o0 = bias + al*k0+a0*k1+a1*k2 + bl*k3+b0*k4+b1*k5 + cl*k6+c0*k7+c1*k8;
        float o1 = bias + a0*k0+a1*k1+a2*k2 + b0*k3+b1*k4+b2*k5 + c0*k6+c1*k7+c2*k8;
        float o2 = bias + a1*k0+a2*k1+a3*k2 + b1*k3+b2*k4+b3*k5 + c1*k6+c2*k7+c3*k8;
        float o3 = bias + a2*k0+a3*k1+ar*k2 + b2*k3+b3*k4+br*k5 + c2*k6+c3*k7+cr*k8;
        *(float4*)(dst + h * RW + w0) =
            make_float4(fmaxf(o0,0.f), fmaxf(o1,0.f), fmaxf(o2,0.f), fmaxf(o3,0.f));
        al=bl; a0=b0; a1=b1; a2=b2; a3=b3; ar=br;
        bl=cl; b0=c0; b1=c1; b2=c2; b3=c3; br=cr;
    }
}

extern "C" __global__ void __launch_bounds__(256, 4)
patnet_kernel(const float* __restrict__ emb,
              const float* __restrict__ conv_w, const float* __restrict__ conv_b,
              const float* __restrict__ ppw_w,  const float* __restrict__ ppw_b,
              const float* __restrict__ pdw_w,  const float* __restrict__ pdw_b,
              const float* __restrict__ pf_w,
              const float* __restrict__ vpw_w,  const float* __restrict__ vpw_b,
              const float* __restrict__ vl1_w,  const float* __restrict__ vl1_b,
              const float* __restrict__ vl2_w,  const float* __restrict__ vl2_b,
              const float* __restrict__ vf_w,   const float* __restrict__ vf_b,
              const int* __restrict__ sparse,   const int* __restrict__ board,
              float* __restrict__ out)
{
    extern __shared__ float sm[];
    float* wdw  = sm + OFF_WDW;
    float* cb   = sm + OFF_CB;
    float* wpd  = sm + OFF_WPD;
    float* bpd  = sm + OFF_BPD;
    float* wpf  = sm + OFF_WPF;
    float* bpp  = sm + OFF_BPP;
    float* bvp  = sm + OFF_BVP;
    float* vsum = sm + OFF_VSUM;
    int*   codes= (int*)(sm + OFF_CODES);
    float* wppT = sm + OFF_WPPT;
    float* wvpT = sm + OFF_WVPT;
    float* raw  = sm + OFF_RAW;
    float* conv = raw;                 // main depthwise IN PLACE
    float* pp   = raw;                 // policy pointwise IN PLACE on rows 0..15
    float* pd   = raw + 16 * STR2;     // value rows 16..31, dead after P3a

    const int tid = threadIdx.x;
    const int b   = blockIdx.x;
    const int lane = tid & 31;

    // ---------- P0: weights -> smem, codes ----------
    for (int i = tid; i < 432; i += 256) wdw[i] = conv_w[i];
    for (int i = tid; i < 48;  i += 256) cb[i]  = conv_b[i];
    for (int i = tid; i < 144; i += 256) wpd[i] = pdw_w[i];
    if (tid < 16) { bpd[tid] = pdw_b[tid]; wpf[tid] = pf_w[tid]; bpp[tid] = ppw_b[tid]; }
    if (tid >= 32 && tid < 64) { bvp[tid-32] = vpw_b[tid-32]; vsum[tid-32] = 0.0f; }
    for (int i = tid; i < 256; i += 256) {
        int co = i >> 4, ci = i & 15;
        wppT[ci * 16 + co] = ppw_w[i];
    }
    for (int i = tid; i < 1024; i += 256) {
        int co = i >> 5, ci = i & 31;
        wvpT[ci * 32 + co] = vpw_w[i];
    }
    for (int i = tid; i < 450; i += 256) {
        int j = i / 225, p = i - j * 225;
        int sp = sparse[b * 2700 + (10 + j) * 225 + p];
        int bd = board[b * 450 + j * 225 + p];
        int c = (bd > 0) ? PC : sp;
        codes[i] = c + j * (PC + 1);
    }
    __syncthreads();

    // ---------- P1: gather all 48 ch, register transpose, vector STS ----------
    if (tid < 240) {
        #pragma unroll
        for (int task = 0; task < 3; task++) {
            const int t = tid + task * 240;
            const int cblk = t / 60, g = t - cblk * 60;
            const int h = g >> 2, w0 = (g & 3) * 4;
            const int cb4 = cblk * 4;
            float4 v[4];
            #pragma unroll
            for (int j = 0; j < 4; j++) {
                int w = w0 + j;
                if (w < 15) {
                    int p = h * 15 + w;
                    int c0 = codes[p], c1 = codes[225 + p];
                    float4 a = *(const float4*)(emb + c0 * 48 + cb4);
                    float4 bb = *(const float4*)(emb + c1 * 48 + cb4);
                    v[j] = make_float4(a.x+bb.x, a.y+bb.y, a.z+bb.z, a.w+bb.w);
                } else v[j] = make_float4(0.f, 0.f, 0.f, 0.f);
            }
            float* base = raw + h * RW + w0;
            *(float4*)(base + (cb4+0)*STR2) = make_float4(v[0].x, v[1].x, v[2].x, v[3].x);
            *(float4*)(base + (cb4+1)*STR2) = make_float4(v[0].y, v[1].y, v[2].y, v[3].y);
            *(float4*)(base + (cb4+2)*STR2) = make_float4(v[0].z, v[1].z, v[2].z, v[3].z);
            *(float4*)(base + (cb4+3)*STR2) = make_float4(v[0].w, v[1].w, v[2].w, v[3].w);
        }
    }
    __syncthreads();

    // ---------- P2: main depthwise 3x3, 48 ch, 192 threads, IN PLACE ----------
    if (tid < 192) {
        const int c = tid >> 2, wg = tid & 3;
        dwconv4<0, 15>(raw + c * STR2, conv + c * STR2, wdw + c * 9, cb[c], wg);
    }
    __syncthreads();

    // ---------- P3a: value 1x1 32->32, f32x2, S=8 C=4, all 256 threads ----------
    {
        const int cg = tid & 7, pgi = tid >> 3;
        const bool live = (pgi < 30);
        const int p0 = live ? pgi * 8 : 0;
        const int co0 = cg * 4;
        ull acc[4][4];
        {
            float4 bv = *(const float4*)&bvp[co0];
            ull b0 = pk2(bv.x, bv.x), b1 = pk2(bv.y, bv.y);
            ull b2 = pk2(bv.z, bv.z), b3 = pk2(bv.w, bv.w);
            #pragma unroll
            for (int j = 0; j < 4; j++) {
                acc[j][0] = b0; acc[j][1] = b1; acc[j][2] = b2; acc[j][3] = b3;
            }
        }
        #pragma unroll 8
        for (int ci = 0; ci < 32; ci++) {
            const ulonglong2* ip = (const ulonglong2*)&conv[(16 + ci) * STR2 + p0];
            float4 w4 = *(const float4*)&wvpT[ci * 32 + co0];
            ull w0 = pk2(w4.x, w4.x), w1 = pk2(w4.y, w4.y);
            ull w2 = pk2(w4.z, w4.z), w3 = pk2(w4.w, w4.w);
            {   // consume first input half before loading second (reg pressure)
                ulonglong2 iA = ip[0];
                ffma2(acc[0][0], iA.x, w0); ffma2(acc[1][0], iA.y, w0);
                ffma2(acc[0][1], iA.x, w1); ffma2(acc[1][1], iA.y, w1);
                ffma2(acc[0][2], iA.x, w2); ffma2(acc[1][2], iA.y, w2);
                ffma2(acc[0][3], iA.x, w3); ffma2(acc[1][3], iA.y, w3);
            }
            {
                ulonglong2 iB = ip[1];
                ffma2(acc[2][0], iB.x, w0); ffma2(acc[3][0], iB.y, w0);
                ffma2(acc[2][1], iB.x, w1); ffma2(acc[3][1], iB.y, w1);
                ffma2(acc[2][2], iB.x, w2); ffma2(acc[3][2], iB.y, w2);
                ffma2(acc[2][3], iB.x, w3); ffma2(acc[3][3], iB.y, w3);
            }
        }
        #pragma unroll
        for (int k = 0; k < 4; k++) {
            float s = 0.0f;
            #pragma unroll
            for (int j = 0; j < 4; j++) {
                float2 f = unpk(acc[j][k]);
                int s0 = p0 + 2 * j;
                if (live && ((s0 & 15) != 15))       s += fmaxf(f.x, 0.0f);
                if (live && (((s0 + 1) & 15) != 15)) s += fmaxf(f.y, 0.0f);
            }
            s += __shfl_xor_sync(0xffffffffu, s, 8);
            s += __shfl_xor_sync(0xffffffffu, s, 16);
            if (lane < 8) atomicAdd(&vsum[lane * 4 + k], s);
        }
    }

    // ---------- P3b: policy 1x1 16->16, IN PLACE on rows 0..15, tid<120 ----------
    // Safe: each thread loads all its inputs before storing; threads sharing a
    // slot range are lanes of one warp (lockstep); other warps use disjoint slots.
    if (tid < 120) {
        const int pgi = tid >> 2, cg = tid & 3;
        const int p0 = pgi * 8, co0 = cg * 4;
        ull acc[4][4];
        {
            float4 bv = *(const float4*)&bpp[co0];
            ull b0 = pk2(bv.x, bv.x), b1 = pk2(bv.y, bv.y);
            ull b2 = pk2(bv.z, bv.z), b3 = pk2(bv.w, bv.w);
            #pragma unroll
            for (int j = 0; j < 4; j++) {
                acc[j][0] = b0; acc[j][1] = b1; acc[j][2] = b2; acc[j][3] = b3;
            }
        }
        #pragma unroll
        for (int ci = 0; ci < 16; ci++) {
            const ulonglong2* ip = (const ulonglong2*)&conv[ci * STR2 + p0];
            ulonglong2 iA = ip[0], iB = ip[1];
            float4 w4 = *(const float4*)&wppT[ci * 16 + co0];
            ull w0 = pk2(w4.x, w4.x), w1 = pk2(w4.y, w4.y);
            ull w2 = pk2(w4.z, w4.z), w3 = pk2(w4.w, w4.w);
            ffma2(acc[0][0], iA.x, w0); ffma2(acc[1][0], iA.y, w0);
            ffma2(acc[2][0], iB.x, w0); ffma2(acc[3][0], iB.y, w0);
            ffma2(acc[0][1], iA.x, w1); ffma2(acc[1][1], iA.y, w1);
            ffma2(acc[2][1], iB.x, w1); ffma2(acc[3][1], iB.y, w1);
            ffma2(acc[0][2], iA.x, w2); ffma2(acc[1][2], iA.y, w2);
            ffma2(acc[2][2], iB.x, w2); ffma2(acc[3][2], iB.y, w2);
            ffma2(acc[0][3], iA.x, w3); ffma2(acc[1][3], iA.y, w3);
            ffma2(acc[2][3], iB.x, w3); ffma2(acc[3][3], iB.y, w3);
        }
        const bool ghost = ((p0 & 15) == 8);   // slot p0+7 is ghost
        #pragma unroll
        for (int k = 0; k < 4; k++) {
            float2 f0 = unpk(acc[0][k]), f1 = unpk(acc[1][k]);
            float2 f2 = unpk(acc[2][k]), f3 = unpk(acc[3][k]);
            float4 oA = make_float4(fmaxf(f0.x,0.f), fmaxf(f0.y,0.f),
                                    fmaxf(f1.x,0.f), fmaxf(f1.y,0.f));
            float4 oB = make_float4(fmaxf(f2.x,0.f), fmaxf(f2.y,0.f),
                                    fmaxf(f3.x,0.f), ghost ? 0.f : fmaxf(f3.y,0.f));
            float* dstc = pp + (co0 + k) * STR2 + p0;
            *(float4*)(dstc)     = oA;
            *(float4*)(dstc + 4) = oB;
        }
    }
    __syncthreads();

    // ---------- P4: policy depthwise (tid<128, row-split) | value FC (warp 7) ----------
    if (tid < 128) {
        const int c = tid >> 3, sub = tid & 7;
        const int wg = sub & 3, half = sub >> 2;
        if (half == 0)
            dwconv4<0, 8>(pp + c * STR2, pd + c * STR2, wpd + c * 9, bpd[c], wg);
        else
            dwconv4<8, 15>(pp + c * STR2, pd + c * STR2, wpd + c * 9, bpd[c], wg);
    }
    if (tid >= 224) {
        const int l = lane;
        float v = vsum[l] * (1.0f / 225.0f);
        float h1 = vl1_b[l];
        #pragma unroll
        for (int i = 0; i < 32; i++)
            h1 += vl1_w[l * 32 + i] * __shfl_sync(0xffffffffu, v, i);
        h1 = fmaxf(h1, 0.0f);
        float h2 = vl2_b[l];
        #pragma unroll
        for (int i = 0; i < 32; i++)
            h2 += vl2_w[l * 32 + i] * __shfl_sync(0xffffffffu, h1, i);
        h2 = fmaxf(h2, 0.0f);
        float o = (l < 3) ? vf_b[l] : 0.0f;
        #pragma unroll
        for (int i = 0; i < 32; i++) {
            float t = __shfl_sync(0xffffffffu, h2, i);
            if (l < 3) o += vf_w[l * 32 + i] * t;
        }
        if (l < 3) out[b * 3 + l] = o;
    }
    __syncthreads();

    // ---------- P5: pf 16->1, f32x2, tid<120 (2 slots each) ----------
    if (tid < 120) {
        const int s0 = 2 * tid;
        ull acc = 0;
        #pragma unroll
        for (int ci = 0; ci < 16; ci++) {
            ull iv = *(const ull*)&pd[ci * STR2 + s0];
            ffma2(acc, iv, pk2(wpf[ci], wpf[ci]));
        }
        float2 f = unpk(acc);
        const int w = s0 & 15, h = s0 >> 4;
        float* ob = out + BATCH * 3 + b * 225 + h * 15 + w;
        ob[0] = f.x;
        if (w < 14) ob[1] = f.y;
    }
}

extern "C" void kernel_launch(void* const* d_in, const int* in_sizes, int n_in,
                              void* d_out, int out_size) {
    (void)in_sizes; (void)n_in; (void)out_size;
    cudaFuncSetAttribute(patnet_kernel,
                         cudaFuncAttributeMaxDynamicSharedMemorySize, SMEM_BYTES);
    patnet_kernel<<<BATCH, 256, SMEM_BYTES>>>(
        (const float*)d_in[0],  (const float*)d_in[1],  (const float*)d_in[2],
        (const float*)d_in[3],  (const float*)d_in[4],  (const float*)d_in[5],
        (const float*)d_in[6],  (const float*)d_in[7],  (const float*)d_in[8],
        (const float*)d_in[9],  (const float*)d_in[10], (const float*)d_in[11],
        (const float*)d_in[12], (const float*)d_in[13], (const float*)d_in[14],
        (const float*)d_in[15], (const int*)d_in[16],   (const int*)d_in[17],
        (float*)d_out);
}

// round 12
// speedup vs baseline: 1.4239x; 1.0547x over previous
#include <cuda_runtime.h>

#define BATCH 4096
#define PC 2380
#define RW 16            // padded row width (15 cols + ghost)
#define STR2 244         // channel stride in floats (mult of 4)

// ---- smem layout (float offsets) ----
#define OFF_CB    0      // 48   conv_b
#define OFF_VSUM  48     // 32
#define OFF_CODES 80     // 450 ints -> 530 (pad to 532)
#define OFF_WPPT  532    // 256   ppw transposed [ci][co]
#define OFF_WVPT  788    // 1024  vpw transposed [ci][co]
#define OFF_STAG  1812   // 768   gather staging: 16 slots x 48 ch (pos-major)
#define OFF_RAW   2580   // 48*244 = 11712 ; depthwise IN PLACE; pol-pw IN PLACE rows 0..15
#define SMEM_FLOATS 14292
#define SMEM_BYTES  (SMEM_FLOATS * 4)

typedef unsigned long long ull;

__device__ __forceinline__ void ffma2(ull& d, ull a, ull b) {
    asm("fma.rn.f32x2 %0, %1, %2, %0;" : "+l"(d) : "l"(a), "l"(b));
}
__device__ __forceinline__ ull pk2(float x, float y) {
    ull r; asm("mov.b64 %0, {%1, %2};" : "=l"(r) : "f"(x), "f"(y)); return r;
}
__device__ __forceinline__ float2 unpk(ull v) {
    float2 f; asm("mov.b64 {%0, %1}, %2;" : "=f"(f.x), "=f"(f.y) : "l"(v)); return f;
}

// depthwise 3x3, one channel, 4-col strip, rows [H0,H1), sliding register window.
// Safe in-place (src==dst): row h+1 is loaded before row h is stored, and all 4
// strips of a channel sit in one warp (lockstep program order).
// wk may point to GLOBAL memory (weights evicted from smem for staging space).
template<int H0, int H1>
__device__ __forceinline__ void dwconv4(const float* src, float* dst,
                                        const float* __restrict__ wk,
                                        float bias, int wg)
{
    const int w0 = wg * 4;
    const bool hasL = (wg > 0), hasR = (wg < 3);
    const float k0=wk[0],k1=wk[1],k2=wk[2],k3=wk[3],k4=wk[4],k5=wk[5],k6=wk[6],k7=wk[7],k8=wk[8];
    float al,a0,a1,a2,a3,ar, bl,b0,b1,b2,b3,br;
    if (H0 > 0) {
        const float* r = src + (H0 - 1) * RW;
        float4 m = *(const float4*)(r + w0);
        al = hasL ? r[w0 - 1] : 0.f;  ar = hasR ? r[w0 + 4] : 0.f;
        a0 = m.x; a1 = m.y; a2 = m.z; a3 = m.w;
    } else { al=a0=a1=a2=a3=ar=0.f; }
    {
        const float* r = src + H0 * RW;
        float4 m = *(const float4*)(r + w0);
        bl = hasL ? r[w0 - 1] : 0.f;  br = hasR ? r[w0 + 4] : 0.f;
        b0 = m.x; b1 = m.y; b2 = m.z; b3 = m.w;
    }
    #pragma unroll
    for (int h = H0; h < H1; h++) {
        float cl, c0, c1, c2, c3, cr;
        if (h + 1 < 15) {
            const float* r = src + (h + 1) * RW;
            float4 m = *(const float4*)(r + w0);
            cl = hasL ? r[w0 - 1] : 0.f;  cr = hasR ? r[w0 + 4] : 0.f;
            c0 = m.x; c1 = m.y; c2 = m.z; c3 = m.w;
        } else { cl = c0 = c1 = c2 = c3 = cr = 0.f; }
        float o0 = bias + al*k0+a0*k1+a1*k2 + bl*k3+b0*k4+b1*k5 + cl*k6+c0*k7+c1*k8;
        float o1 = bias + a0*k0+a1*k1+a2*k2 + b0*k3+b1*k4+b2*k5 + c0*k6+c1*k7+c2*k8;
        float o2 = bias + a1*k0+a2*k1+a3*k2 + b1*k3+b2*k4+b3*k5 + c1*k6+c2*k7+c3*k8;
        float o3 = bias + a2*k0+a3*k1+ar*k2 + b2*k3+b3*k4+br*k5 + c2*k6+c3*k7+cr*k8;
        *(float4*)(dst + h * RW + w0) =
            make_float4(fmaxf(o0,0.f), fmaxf(o1,0.f), fmaxf(o2,0.f), fmaxf(o3,0.f));
        al=bl; a0=b0; a1=b1; a2=b2; a3=b3; ar=br;
        bl=cl; b0=c0; b1=c1; b2=c2; b3=c3; br=cr;
    }
}

extern "C" __global__ void __launch_bounds__(256, 4)
patnet_kernel(const float* __restrict__ emb,
              const float* __restrict__ conv_w, const float* __restrict__ conv_b,
              const float* __restrict__ ppw_w,  const float* __restrict__ ppw_b,
              const float* __restrict__ pdw_w,  const float* __restrict__ pdw_b,
              const float* __restrict__ pf_w,
              const float* __restrict__ vpw_w,  const float* __restrict__ vpw_b,
              const float* __restrict__ vl1_w,  const float* __restrict__ vl1_b,
              const float* __restrict__ vl2_w,  const float* __restrict__ vl2_b,
              const float* __restrict__ vf_w,   const float* __restrict__ vf_b,
              const int* __restrict__ sparse,   const int* __restrict__ board,
              float* __restrict__ out)
{
    extern __shared__ float sm[];
    float* cb   = sm + OFF_CB;
    float* vsum = sm + OFF_VSUM;
    int*   codes= (int*)(sm + OFF_CODES);
    float* wppT = sm + OFF_WPPT;
    float* wvpT = sm + OFF_WVPT;
    float* stag = sm + OFF_STAG;
    float* raw  = sm + OFF_RAW;
    float* conv = raw;                 // main depthwise IN PLACE
    float* pp   = raw;                 // policy pointwise IN PLACE on rows 0..15
    float* pd   = raw + 16 * STR2;     // value rows 16..31, dead after P3a

    const int tid = threadIdx.x;
    const int b   = blockIdx.x;
    const int lane = tid & 31;

    // ---------- P0: small weights -> smem, codes ----------
    for (int i = tid; i < 48;  i += 256) cb[i]  = conv_b[i];
    if (tid >= 64 && tid < 96) vsum[tid-64] = 0.0f;
    for (int i = tid; i < 256; i += 256) {
        int co = i >> 4, ci = i & 15;
        wppT[ci * 16 + co] = ppw_w[i];
    }
    for (int i = tid; i < 1024; i += 256) {
        int co = i >> 5, ci = i & 31;
        wvpT[ci * 32 + co] = vpw_w[i];
    }
    for (int i = tid; i < 450; i += 256) {
        int j = i / 225, p = i - j * 225;
        int sp = sparse[b * 2700 + (10 + j) * 225 + p];
        int bd = board[b * 450 + j * 225 + p];
        int c = (bd > 0) ? PC : sp;
        codes[i] = c + j * (PC + 1);
    }
    __syncthreads();

    // ---------- P1: staged gather, one board row per round ----------
    // stage: coalesced LDG (lanes sweep quarters of consecutive rows), sum codes
    //        locally, STS.128 into pos-major staging [slot][48].
    // transpose: conflict-free scalar LDS + vector STS into ch-major raw.
    #pragma unroll 1
    for (int r = 0; r < 15; r++) {
        if (tid < 192) {
            const int sl = tid / 12, q = tid - sl * 12;   // sl = w (0..15), q = quarter
            float4 v = make_float4(0.f, 0.f, 0.f, 0.f);
            if (sl < 15) {
                const int p = r * 15 + sl;
                const int c0 = codes[p], c1 = codes[225 + p];
                float4 a  = *(const float4*)(emb + c0 * 48 + q * 4);
                float4 b2 = *(const float4*)(emb + c1 * 48 + q * 4);
                v = make_float4(a.x + b2.x, a.y + b2.y, a.z + b2.z, a.w + b2.w);
            }
            *(float4*)&stag[sl * 48 + q * 4] = v;
        }
        __syncthreads();
        if (tid < 192) {
            const int g = tid / 48, c = tid - g * 48;     // g = slot-group, c = channel
            float4 o;
            o.x = stag[(4*g + 0) * 48 + c];
            o.y = stag[(4*g + 1) * 48 + c];
            o.z = stag[(4*g + 2) * 48 + c];
            o.w = stag[(4*g + 3) * 48 + c];
            *(float4*)&raw[c * STR2 + r * RW + 4 * g] = o;
        }
        __syncthreads();
    }

    // ---------- P2: main depthwise 3x3, 48 ch, 192 threads, IN PLACE ----------
    if (tid < 192) {
        const int c = tid >> 2, wg = tid & 3;
        dwconv4<0, 15>(raw + c * STR2, conv + c * STR2, conv_w + c * 9, cb[c], wg);
    }
    __syncthreads();

    // ---------- P3a: value 1x1 32->32, f32x2, S=8 C=4, all 256 threads ----------
    {
        const int cg = tid & 7, pgi = tid >> 3;
        const bool live = (pgi < 30);
        const int p0 = live ? pgi * 8 : 0;
        const int co0 = cg * 4;
        ull acc[4][4];
        {
            float4 bv = *(const float4*)&vpw_b[co0];
            ull b0 = pk2(bv.x, bv.x), b1 = pk2(bv.y, bv.y);
            ull b2 = pk2(bv.z, bv.z), b3 = pk2(bv.w, bv.w);
            #pragma unroll
            for (int j = 0; j < 4; j++) {
                acc[j][0] = b0; acc[j][1] = b1; acc[j][2] = b2; acc[j][3] = b3;
            }
        }
        #pragma unroll 8
        for (int ci = 0; ci < 32; ci++) {
            const ulonglong2* ip = (const ulonglong2*)&conv[(16 + ci) * STR2 + p0];
            float4 w4 = *(const float4*)&wvpT[ci * 32 + co0];
            ull w0 = pk2(w4.x, w4.x), w1 = pk2(w4.y, w4.y);
            ull w2 = pk2(w4.z, w4.z), w3 = pk2(w4.w, w4.w);
            {
                ulonglong2 iA = ip[0];
                ffma2(acc[0][0], iA.x, w0); ffma2(acc[1][0], iA.y, w0);
                ffma2(acc[0][1], iA.x, w1); ffma2(acc[1][1], iA.y, w1);
                ffma2(acc[0][2], iA.x, w2); ffma2(acc[1][2], iA.y, w2);
                ffma2(acc[0][3], iA.x, w3); ffma2(acc[1][3], iA.y, w3);
            }
            {
                ulonglong2 iB = ip[1];
                ffma2(acc[2][0], iB.x, w0); ffma2(acc[3][0], iB.y, w0);
                ffma2(acc[2][1], iB.x, w1); ffma2(acc[3][1], iB.y, w1);
                ffma2(acc[2][2], iB.x, w2); ffma2(acc[3][2], iB.y, w2);
                ffma2(acc[2][3], iB.x, w3); ffma2(acc[3][3], iB.y, w3);
            }
        }
        #pragma unroll
        for (int k = 0; k < 4; k++) {
            float s = 0.0f;
            #pragma unroll
            for (int j = 0; j < 4; j++) {
                float2 f = unpk(acc[j][k]);
                int s0 = p0 + 2 * j;
                if (live && ((s0 & 15) != 15))       s += fmaxf(f.x, 0.0f);
                if (live && (((s0 + 1) & 15) != 15)) s += fmaxf(f.y, 0.0f);
            }
            s += __shfl_xor_sync(0xffffffffu, s, 8);
            s += __shfl_xor_sync(0xffffffffu, s, 16);
            if (lane < 8) atomicAdd(&vsum[lane * 4 + k], s);
        }
    }

    // ---------- P3b: policy 1x1 16->16, IN PLACE on rows 0..15, tid<120 ----------
    if (tid < 120) {
        const int pgi = tid >> 2, cg = tid & 3;
        const int p0 = pgi * 8, co0 = cg * 4;
        ull acc[4][4];
        {
            float4 bv = *(const float4*)&ppw_b[co0];
            ull b0 = pk2(bv.x, bv.x), b1 = pk2(bv.y, bv.y);
            ull b2 = pk2(bv.z, bv.z), b3 = pk2(bv.w, bv.w);
            #pragma unroll
            for (int j = 0; j < 4; j++) {
                acc[j][0] = b0; acc[j][1] = b1; acc[j][2] = b2; acc[j][3] = b3;
            }
        }
        #pragma unroll
        for (int ci = 0; ci < 16; ci++) {
            const ulonglong2* ip = (const ulonglong2*)&conv[ci * STR2 + p0];
            ulonglong2 iA = ip[0], iB = ip[1];
            float4 w4 = *(const float4*)&wppT[ci * 16 + co0];
            ull w0 = pk2(w4.x, w4.x), w1 = pk2(w4.y, w4.y);
            ull w2 = pk2(w4.z, w4.z), w3 = pk2(w4.w, w4.w);
            ffma2(acc[0][0], iA.x, w0); ffma2(acc[1][0], iA.y, w0);
            ffma2(acc[2][0], iB.x, w0); ffma2(acc[3][0], iB.y, w0);
            ffma2(acc[0][1], iA.x, w1); ffma2(acc[1][1], iA.y, w1);
            ffma2(acc[2][1], iB.x, w1); ffma2(acc[3][1], iB.y, w1);
            ffma2(acc[0][2], iA.x, w2); ffma2(acc[1][2], iA.y, w2);
            ffma2(acc[2][2], iB.x, w2); ffma2(acc[3][2], iB.y, w2);
            ffma2(acc[0][3], iA.x, w3); ffma2(acc[1][3], iA.y, w3);
            ffma2(acc[2][3], iB.x, w3); ffma2(acc[3][3], iB.y, w3);
        }
        const bool ghost = ((p0 & 15) == 8);   // slot p0+7 is ghost
        #pragma unroll
        for (int k = 0; k < 4; k++) {
            float2 f0 = unpk(acc[0][k]), f1 = unpk(acc[1][k]);
            float2 f2 = unpk(acc[2][k]), f3 = unpk(acc[3][k]);
            float4 oA = make_float4(fmaxf(f0.x,0.f), fmaxf(f0.y,0.f),
                                    fmaxf(f1.x,0.f), fmaxf(f1.y,0.f));
            float4 oB = make_float4(fmaxf(f2.x,0.f), fmaxf(f2.y,0.f),
                                    fmaxf(f3.x,0.f), ghost ? 0.f : fmaxf(f3.y,0.f));
            float* dstc = pp + (co0 + k) * STR2 + p0;
            *(float4*)(dstc)     = oA;
            *(float4*)(dstc + 4) = oB;
        }
    }
    __syncthreads();

    // ---------- P4: policy depthwise (tid<128, row-split) | value FC (warp 7) ----------
    if (tid < 128) {
        const int c = tid >> 3, sub = tid & 7;
        const int wg = sub & 3, half = sub >> 2;
        const float bias = pdw_b[c];
        if (half == 0)
            dwconv4<0, 8>(pp + c * STR2, pd + c * STR2, pdw_w + c * 9, bias, wg);
        else
            dwconv4<8, 15>(pp + c * STR2, pd + c * STR2, pdw_w + c * 9, bias, wg);
    }
    if (tid >= 224) {
        const int l = lane;
        float v = vsum[l] * (1.0f / 225.0f);
        float h1 = vl1_b[l];
        #pragma unroll
        for (int i = 0; i < 32; i++)
            h1 += vl1_w[l * 32 + i] * __shfl_sync(0xffffffffu, v, i);
        h1 = fmaxf(h1, 0.0f);
        float h2 = vl2_b[l];
        #pragma unroll
        for (int i = 0; i < 32; i++)
            h2 += vl2_w[l * 32 + i] * __shfl_sync(0xffffffffu, h1, i);
        h2 = fmaxf(h2, 0.0f);
        float o = (l < 3) ? vf_b[l] : 0.0f;
        #pragma unroll
        for (int i = 0; i < 32; i++) {
            float t = __shfl_sync(0xffffffffu, h2, i);
            if (l < 3) o += vf_w[l * 32 + i] * t;
        }
        if (l < 3) out[b * 3 + l] = o;
    }
    __syncthreads();

    // ---------- P5: pf 16->1, f32x2, tid<120 (2 slots each) ----------
    if (tid < 120) {
        const int s0 = 2 * tid;
        const float4 wfA = *(const float4*)(pf_w);
        const float4 wfB = *(const float4*)(pf_w + 4);
        const float4 wfC = *(const float4*)(pf_w + 8);
        const float4 wfD = *(const float4*)(pf_w + 12);
        const float wf[16] = {wfA.x,wfA.y,wfA.z,wfA.w, wfB.x,wfB.y,wfB.z,wfB.w,
                              wfC.x,wfC.y,wfC.z,wfC.w, wfD.x,wfD.y,wfD.z,wfD.w};
        ull acc = 0;
        #pragma unroll
        for (int ci = 0; ci < 16; ci++) {
            ull iv = *(const ull*)&pd[ci * STR2 + s0];
            ffma2(acc, iv, pk2(wf[ci], wf[ci]));
        }
        float2 f = unpk(acc);
        const int w = s0 & 15, h = s0 >> 4;
        float* ob = out + BATCH * 3 + b * 225 + h * 15 + w;
        ob[0] = f.x;
        if (w < 14) ob[1] = f.y;
    }
}

extern "C" void kernel_launch(void* const* d_in, const int* in_sizes, int n_in,
                              void* d_out, int out_size) {
    (void)in_sizes; (void)n_in; (void)out_size;
    cudaFuncSetAttribute(patnet_kernel,
                         cudaFuncAttributeMaxDynamicSharedMemorySize, SMEM_BYTES);
    patnet_kernel<<<BATCH, 256, SMEM_BYTES>>>(
        (const float*)d_in[0],  (const float*)d_in[1],  (const float*)d_in[2],
        (const float*)d_in[3],  (const float*)d_in[4],  (const float*)d_in[5],
        (const float*)d_in[6],  (const float*)d_in[7],  (const float*)d_in[8],
        (const float*)d_in[9],  (const float*)d_in[10], (const float*)d_in[11],
        (const float*)d_in[12], (const float*)d_in[13], (const float*)d_in[14],
        (const float*)d_in[15], (const int*)d_in[16],   (const int*)d_in[17],
        (float*)d_out);
}